// round 1
// baseline (speedup 1.0000x reference)
#include <cuda_runtime.h>
#include <math.h>

#define NN 4096
#define DD 256
#define LL 3
#define ND (NN * DD)

// ---------------- scratch (device globals; no allocation allowed) ----------
__device__ float g_X[ND];
__device__ float g_H1[ND];
__device__ float g_H2[ND];
__device__ float g_Y[ND];
__device__ float g_Hm[ND];
__device__ float g_ACC[ND];
__device__ float g_G[4][ND];
__device__ float g_ADJ[NN * NN];          // 64 MB
__device__ float g_adjpart[64 * 64];      // per-block tile sums of ADJ
__device__ float g_mean;                  // adj mean
__device__ float g_colpart[32 * 512];     // [32 blocks][sum(256) | sumsq(256)]
__device__ float g_bnscale[DD];
__device__ float g_bnshift[DD];
__device__ float g_msepart[256 * 3];

__device__ __forceinline__ float eluf(float x) {
    return x > 0.0f ? x : (expf(x) - 1.0f);
}

// ---------------- GEMM: C[4096,256] = act(A[4096,256] @ W[256,256] + b) -----
// EPI 0: ELU   EPI 1: bias only   EPI 2: bias + write C and ACC += C
template <int EPI>
__global__ __launch_bounds__(256) void gemm_k256(
    const float* __restrict__ A, const float* __restrict__ W,
    const float* __restrict__ bias, float* __restrict__ C,
    float* __restrict__ ACC)
{
    __shared__ float As[16][64];
    __shared__ float Bs[16][64];
    const int tid = threadIdx.x;
    const int tx = tid & 15, ty = tid >> 4;
    const int m0 = blockIdx.y * 64, n0 = blockIdx.x * 64;

    float acc[4][4] = {};
    for (int k0 = 0; k0 < 256; k0 += 16) {
#pragma unroll
        for (int c = 0; c < 4; ++c) {
            int i = c * 256 + tid;
            int m = i >> 4, k = i & 15;
            As[k][m] = A[(m0 + m) * 256 + (k0 + k)];
        }
#pragma unroll
        for (int c = 0; c < 4; ++c) {
            int i = c * 256 + tid;
            int k = i >> 6, n = i & 63;
            Bs[k][n] = W[(k0 + k) * 256 + (n0 + n)];
        }
        __syncthreads();
#pragma unroll
        for (int kk = 0; kk < 16; ++kk) {
            float4 a4 = *reinterpret_cast<const float4*>(&As[kk][ty * 4]);
            float4 b4 = *reinterpret_cast<const float4*>(&Bs[kk][tx * 4]);
            float a[4] = {a4.x, a4.y, a4.z, a4.w};
            float b[4] = {b4.x, b4.y, b4.z, b4.w};
#pragma unroll
            for (int i = 0; i < 4; ++i)
#pragma unroll
                for (int j = 0; j < 4; ++j) acc[i][j] += a[i] * b[j];
        }
        __syncthreads();
    }
#pragma unroll
    for (int i = 0; i < 4; ++i) {
        int m = m0 + ty * 4 + i;
#pragma unroll
        for (int j = 0; j < 4; ++j) {
            int n = n0 + tx * 4 + j;
            float c = acc[i][j] + bias[n];
            if (EPI == 0) c = eluf(c);
            C[m * 256 + n] = c;
            if (EPI == 2) ACC[m * 256 + n] += c;
        }
    }
}

// ---------------- ADJ = H @ H^T (4096x4096, K=256) + per-block tile sums ----
__global__ __launch_bounds__(256) void gemm_nt_adj(const float* __restrict__ H)
{
    __shared__ float As[16][64];
    __shared__ float Bs[16][64];
    const int tid = threadIdx.x;
    const int tx = tid & 15, ty = tid >> 4;
    const int m0 = blockIdx.y * 64, n0 = blockIdx.x * 64;

    float acc[4][4] = {};
    for (int k0 = 0; k0 < 256; k0 += 16) {
#pragma unroll
        for (int c = 0; c < 4; ++c) {
            int i = c * 256 + tid;
            int m = i >> 4, k = i & 15;
            As[k][m] = H[(m0 + m) * 256 + (k0 + k)];
            Bs[k][m] = H[(n0 + m) * 256 + (k0 + k)];
        }
        __syncthreads();
#pragma unroll
        for (int kk = 0; kk < 16; ++kk) {
            float4 a4 = *reinterpret_cast<const float4*>(&As[kk][ty * 4]);
            float4 b4 = *reinterpret_cast<const float4*>(&Bs[kk][tx * 4]);
            float a[4] = {a4.x, a4.y, a4.z, a4.w};
            float b[4] = {b4.x, b4.y, b4.z, b4.w};
#pragma unroll
            for (int i = 0; i < 4; ++i)
#pragma unroll
                for (int j = 0; j < 4; ++j) acc[i][j] += a[i] * b[j];
        }
        __syncthreads();
    }
    float s = 0.0f;
#pragma unroll
    for (int i = 0; i < 4; ++i) {
        int m = m0 + ty * 4 + i;
#pragma unroll
        for (int j = 0; j < 4; ++j) {
            int n = n0 + tx * 4 + j;
            g_ADJ[m * NN + n] = acc[i][j];
            s += acc[i][j];
        }
    }
    __shared__ float red[256];
    red[tid] = s;
    __syncthreads();
    for (int o = 128; o > 0; o >>= 1) {
        if (tid < o) red[tid] += red[tid + o];
        __syncthreads();
    }
    if (tid == 0) g_adjpart[blockIdx.y * 64 + blockIdx.x] = red[0];
}

__global__ void reduce_adjsum()
{
    __shared__ float red[1024];
    int t = threadIdx.x;
    red[t] = g_adjpart[t] + g_adjpart[t + 1024] + g_adjpart[t + 2048] +
             g_adjpart[t + 3072];
    __syncthreads();
    for (int o = 512; o > 0; o >>= 1) {
        if (t < o) red[t] += red[t + o];
        __syncthreads();
    }
    if (t == 0) g_mean = red[0] * (1.0f / ((float)NN * (float)NN));
}

// ---------------- Y = (ADJ > mean) @ X + X  (4096x256, K=4096) --------------
__global__ __launch_bounds__(256) void gemm_thresh(
    const float* __restrict__ X, float* __restrict__ Y)
{
    const float mean = g_mean;
    __shared__ float As[16][64];
    __shared__ float Bs[16][64];
    const int tid = threadIdx.x;
    const int tx = tid & 15, ty = tid >> 4;
    const int m0 = blockIdx.y * 64, n0 = blockIdx.x * 64;

    float acc[4][4] = {};
    for (int k0 = 0; k0 < NN; k0 += 16) {
#pragma unroll
        for (int c = 0; c < 4; ++c) {
            int i = c * 256 + tid;
            int m = i >> 4, k = i & 15;
            As[k][m] = (g_ADJ[(m0 + m) * NN + (k0 + k)] > mean) ? 1.0f : 0.0f;
        }
#pragma unroll
        for (int c = 0; c < 4; ++c) {
            int i = c * 256 + tid;
            int k = i >> 6, n = i & 63;
            Bs[k][n] = X[(k0 + k) * 256 + (n0 + n)];
        }
        __syncthreads();
#pragma unroll
        for (int kk = 0; kk < 16; ++kk) {
            float4 a4 = *reinterpret_cast<const float4*>(&As[kk][ty * 4]);
            float4 b4 = *reinterpret_cast<const float4*>(&Bs[kk][tx * 4]);
            float a[4] = {a4.x, a4.y, a4.z, a4.w};
            float b[4] = {b4.x, b4.y, b4.z, b4.w};
#pragma unroll
            for (int i = 0; i < 4; ++i)
#pragma unroll
                for (int j = 0; j < 4; ++j) acc[i][j] += a[i] * b[j];
        }
        __syncthreads();
    }
#pragma unroll
    for (int i = 0; i < 4; ++i) {
        int m = m0 + ty * 4 + i;
#pragma unroll
        for (int j = 0; j < 4; ++j) {
            int n = n0 + tx * 4 + j;
            Y[m * 256 + n] = acc[i][j] + X[m * 256 + n];  // E = 1.0 eye term
        }
    }
}

// ---------------- BatchNorm stats (deterministic 2-stage) -------------------
__global__ void colstats(const float* __restrict__ H)
{
    int t = threadIdx.x;           // 256 = one column per thread
    int r0 = blockIdx.x * 128;     // 32 blocks * 128 rows
    float s = 0.0f, q = 0.0f;
    for (int r = r0; r < r0 + 128; ++r) {
        float v = H[r * 256 + t];
        s += v;
        q += v * v;
    }
    g_colpart[blockIdx.x * 512 + t] = s;
    g_colpart[blockIdx.x * 512 + 256 + t] = q;
}

__global__ void finalize_stats(const float* __restrict__ gamma,
                               const float* __restrict__ beta)
{
    int t = threadIdx.x;  // 256
    float s = 0.0f, q = 0.0f;
    for (int b = 0; b < 32; ++b) {
        s += g_colpart[b * 512 + t];
        q += g_colpart[b * 512 + 256 + t];
    }
    float mu = s * (1.0f / (float)NN);
    float var = q * (1.0f / (float)NN) - mu * mu;
    float rstd = rsqrtf(var + 1e-5f);
    float sc = gamma[t] * rstd;
    g_bnscale[t] = sc;
    g_bnshift[t] = beta[t] - mu * sc;
}

__global__ void bn_relu(float* __restrict__ H)
{
    int stride = gridDim.x * blockDim.x;
    for (int i = blockIdx.x * blockDim.x + threadIdx.x; i < ND; i += stride) {
        int c = i & 255;
        float h = H[i] * g_bnscale[c] + g_bnshift[c];
        H[i] = fmaxf(h, 0.0f);
    }
}

// ---------------- init / scale / MSE ----------------------------------------
__global__ void init_X_ACC(const float* __restrict__ Xin)
{
    int stride = gridDim.x * blockDim.x;
    for (int i = blockIdx.x * blockDim.x + threadIdx.x; i < ND; i += stride) {
        g_X[i] = Xin[i];
        g_ACC[i] = 0.0f;
    }
}

__global__ void scale_store(int branch)
{
    int stride = gridDim.x * blockDim.x;
    for (int i = blockIdx.x * blockDim.x + threadIdx.x; i < ND; i += stride)
        g_G[branch][i] = g_ACC[i] * (1.0f / 3.0f);
}

__global__ void mse_partial()
{
    int t = threadIdx.x, b = blockIdx.x;
    float s0 = 0.0f, s1 = 0.0f, s2 = 0.0f;
    for (int i = b * 256 + t; i < ND; i += 256 * 256) {
        float ga = g_G[3][i];
        float d0 = g_G[0][i] - ga;
        float d1 = g_G[1][i] - ga;
        float d2 = g_G[2][i] - ga;
        s0 += d0 * d0;
        s1 += d1 * d1;
        s2 += d2 * d2;
    }
    __shared__ float r[3][256];
    r[0][t] = s0; r[1][t] = s1; r[2][t] = s2;
    __syncthreads();
    for (int o = 128; o > 0; o >>= 1) {
        if (t < o) {
            r[0][t] += r[0][t + o];
            r[1][t] += r[1][t + o];
            r[2][t] += r[2][t + o];
        }
        __syncthreads();
    }
    if (t == 0) {
        g_msepart[b * 3 + 0] = r[0][0];
        g_msepart[b * 3 + 1] = r[1][0];
        g_msepart[b * 3 + 2] = r[2][0];
    }
}

__global__ void mse_final(float* __restrict__ out)
{
    int t = threadIdx.x;  // 256
    __shared__ float r[256];
    for (int v = 0; v < 3; ++v) {
        r[t] = g_msepart[t * 3 + v];
        __syncthreads();
        for (int o = 128; o > 0; o >>= 1) {
            if (t < o) r[t] += r[t + o];
            __syncthreads();
        }
        if (t == 0) out[v] = r[0] * (1.0f / (float)ND);
        __syncthreads();
    }
}

// ---------------- host driver ------------------------------------------------
struct Scratch {
    float *X, *H1, *H2, *Y, *Hm, *ACC;
};

static void run_gin(const Scratch& p, const float* Xin,
                    const float* aW, const float* ab,
                    const float* mW, const float* mb, const float* mbn,
                    int branch)
{
    const dim3 g_small(4, 64), g_big(64, 64);
    init_X_ACC<<<1024, 256>>>(Xin);
    for (int l = 0; l < LL; ++l) {
        // adjacency learner
        gemm_k256<0><<<g_small, 256>>>(p.X, aW, ab, p.H1, nullptr);
        gemm_k256<0><<<g_small, 256>>>(p.H1, aW + 65536, ab + 256, p.H2, nullptr);
        gemm_nt_adj<<<g_big, 256>>>(p.H2);
        reduce_adjsum<<<1, 1024>>>();
        // aggregate (oh + I) @ X
        gemm_thresh<<<g_small, 256>>>(p.X, p.Y);
        // GIN MLP
        const float* W0 = mW + (size_t)(l * 2) * 65536;
        const float* W1 = W0 + 65536;
        const float* b0 = mb + l * 2 * 256;
        const float* b1 = b0 + 256;
        const float* gamma = mbn + l * 2 * 256;
        const float* beta = gamma + 256;
        gemm_k256<1><<<g_small, 256>>>(p.Y, W0, b0, p.Hm, nullptr);
        colstats<<<32, 256>>>(p.Hm);
        finalize_stats<<<1, 256>>>(gamma, beta);
        bn_relu<<<1024, 256>>>(p.Hm);
        gemm_k256<2><<<g_small, 256>>>(p.Hm, W1, b1, p.X, p.ACC);
    }
    scale_store<<<1024, 256>>>(branch);
}

extern "C" void kernel_launch(void* const* d_in, const int* in_sizes, int n_in,
                              void* d_out, int out_size)
{
    const float* QV = (const float*)d_in[0];
    const float* Q  = (const float*)d_in[1];
    const float* V  = (const float*)d_in[2];
    const float* A  = (const float*)d_in[3];
    const float* adjW_qv  = (const float*)d_in[4];
    const float* adjb_qv  = (const float*)d_in[5];
    const float* mlpW_qv  = (const float*)d_in[6];
    const float* mlpb_qv  = (const float*)d_in[7];
    const float* mlpbn_qv = (const float*)d_in[8];
    const float* adjW_t   = (const float*)d_in[9];
    const float* adjb_t   = (const float*)d_in[10];
    const float* mlpW_t   = (const float*)d_in[11];
    const float* mlpb_t   = (const float*)d_in[12];
    const float* mlpbn_t  = (const float*)d_in[13];
    const float* adjW_v   = (const float*)d_in[14];
    const float* adjb_v   = (const float*)d_in[15];
    const float* mlpW_v   = (const float*)d_in[16];
    const float* mlpb_v   = (const float*)d_in[17];
    const float* mlpbn_v  = (const float*)d_in[18];

    Scratch p;
    cudaGetSymbolAddress((void**)&p.X, g_X);
    cudaGetSymbolAddress((void**)&p.H1, g_H1);
    cudaGetSymbolAddress((void**)&p.H2, g_H2);
    cudaGetSymbolAddress((void**)&p.Y, g_Y);
    cudaGetSymbolAddress((void**)&p.Hm, g_Hm);
    cudaGetSymbolAddress((void**)&p.ACC, g_ACC);

    run_gin(p, QV, adjW_qv, adjb_qv, mlpW_qv, mlpb_qv, mlpbn_qv, 0);
    run_gin(p, Q,  adjW_t,  adjb_t,  mlpW_t,  mlpb_t,  mlpbn_t,  1);
    run_gin(p, V,  adjW_v,  adjb_v,  mlpW_v,  mlpb_v,  mlpbn_v,  2);
    run_gin(p, A,  adjW_t,  adjb_t,  mlpW_t,  mlpb_t,  mlpbn_t,  3);

    mse_partial<<<256, 256>>>();
    mse_final<<<1, 256>>>((float*)d_out);
}

// round 2
// speedup vs baseline: 2.1621x; 2.1621x over previous
#include <cuda_runtime.h>
#include <math.h>

#define NN 4096
#define DD 256
#define LL 3
#define ND (NN * DD)
#define NTB 528   // 32*33/2 upper-triangular 128x128 tiles

// ---------------- scratch (device globals; no allocation allowed) ----------
__device__ float g_X[ND];
__device__ float g_H1[ND];
__device__ float g_H2[ND];
__device__ float g_Y[ND];
__device__ float g_Hm[ND];
__device__ float g_ACC[ND];
__device__ float g_G[4][ND];
__device__ float g_ADJ[NN * NN];          // 64 MB
__device__ float g_Yp[4 * ND];            // split-K partials, 16 MB
__device__ float g_adjpart[NTB];
__device__ float g_mean;
__device__ float g_colpart[32 * 512];
__device__ float g_bnscale[DD];
__device__ float g_bnshift[DD];
__device__ float g_msepart[256 * 3];

__device__ __forceinline__ float eluf(float x) {
    return x > 0.0f ? x : (expf(x) - 1.0f);
}

// ---------------- GEMM: C[4096,256] = act(A[4096,256] @ W[256,256] + b) -----
// EPI 0: ELU   EPI 1: bias only   EPI 2: bias + write C and ACC += C
template <int EPI>
__global__ __launch_bounds__(256) void gemm_k256(
    const float* __restrict__ A, const float* __restrict__ W,
    const float* __restrict__ bias, float* __restrict__ C,
    float* __restrict__ ACC)
{
    __shared__ float As[16][64];
    __shared__ float Bs[16][64];
    const int tid = threadIdx.x;
    const int tx = tid & 15, ty = tid >> 4;
    const int m0 = blockIdx.y * 64, n0 = blockIdx.x * 64;

    float acc[4][4] = {};
    for (int k0 = 0; k0 < 256; k0 += 16) {
#pragma unroll
        for (int c = 0; c < 4; ++c) {
            int i = c * 256 + tid;
            int m = i >> 4, k = i & 15;
            As[k][m] = A[(m0 + m) * 256 + (k0 + k)];
        }
#pragma unroll
        for (int c = 0; c < 4; ++c) {
            int i = c * 256 + tid;
            int k = i >> 6, n = i & 63;
            Bs[k][n] = W[(k0 + k) * 256 + (n0 + n)];
        }
        __syncthreads();
#pragma unroll
        for (int kk = 0; kk < 16; ++kk) {
            float4 a4 = *reinterpret_cast<const float4*>(&As[kk][ty * 4]);
            float4 b4 = *reinterpret_cast<const float4*>(&Bs[kk][tx * 4]);
            float a[4] = {a4.x, a4.y, a4.z, a4.w};
            float b[4] = {b4.x, b4.y, b4.z, b4.w};
#pragma unroll
            for (int i = 0; i < 4; ++i)
#pragma unroll
                for (int j = 0; j < 4; ++j) acc[i][j] += a[i] * b[j];
        }
        __syncthreads();
    }
#pragma unroll
    for (int i = 0; i < 4; ++i) {
        int m = m0 + ty * 4 + i;
#pragma unroll
        for (int j = 0; j < 4; ++j) {
            int n = n0 + tx * 4 + j;
            float c = acc[i][j] + bias[n];
            if (EPI == 0) c = eluf(c);
            C[m * 256 + n] = c;
            if (EPI == 2) ACC[m * 256 + n] += c;
        }
    }
}

// ---------------- ADJ = H @ H^T, symmetric: 528 upper 128x128 tiles ---------
__global__ __launch_bounds__(256, 2) void gemm_nt_sym(const float* __restrict__ H)
{
    // map linear block id -> (bi <= bj)
    int b = blockIdx.x;
    int bi = 0, rem = b;
    while (rem >= 32 - bi) { rem -= 32 - bi; ++bi; }
    const int bj = bi + rem;
    const int m0 = bi * 128, n0 = bj * 128;

    __shared__ __align__(16) float As[2][8][128];
    __shared__ __align__(16) float Bs[2][8][128];
    __shared__ float red[256];

    const int tid = threadIdx.x;
    const int tx4 = (tid & 15) * 4;
    const int ty4 = (tid >> 4) * 4;
    const int lrow = tid >> 1, lk = (tid & 1) * 4;

    const float* pA = H + (m0 + lrow) * 256 + lk;
    const float* pB = H + (n0 + lrow) * 256 + lk;

    float acc[8][8] = {};
    float4 ra = *reinterpret_cast<const float4*>(pA);
    float4 rb = *reinterpret_cast<const float4*>(pB);

    int buf = 0;
    As[0][lk + 0][lrow] = ra.x; As[0][lk + 1][lrow] = ra.y;
    As[0][lk + 2][lrow] = ra.z; As[0][lk + 3][lrow] = ra.w;
    Bs[0][lk + 0][lrow] = rb.x; Bs[0][lk + 1][lrow] = rb.y;
    Bs[0][lk + 2][lrow] = rb.z; Bs[0][lk + 3][lrow] = rb.w;
    __syncthreads();

    for (int c = 0; c < 32; ++c) {
        if (c < 31) {
            ra = *reinterpret_cast<const float4*>(pA + (c + 1) * 8);
            rb = *reinterpret_cast<const float4*>(pB + (c + 1) * 8);
        }
#pragma unroll
        for (int kk = 0; kk < 8; ++kk) {
            float4 a0 = *reinterpret_cast<const float4*>(&As[buf][kk][ty4]);
            float4 a1 = *reinterpret_cast<const float4*>(&As[buf][kk][ty4 + 64]);
            float4 b0 = *reinterpret_cast<const float4*>(&Bs[buf][kk][tx4]);
            float4 b1 = *reinterpret_cast<const float4*>(&Bs[buf][kk][tx4 + 64]);
            float a[8] = {a0.x, a0.y, a0.z, a0.w, a1.x, a1.y, a1.z, a1.w};
            float bb[8] = {b0.x, b0.y, b0.z, b0.w, b1.x, b1.y, b1.z, b1.w};
#pragma unroll
            for (int i = 0; i < 8; ++i)
#pragma unroll
                for (int j = 0; j < 8; ++j) acc[i][j] += a[i] * bb[j];
        }
        if (c < 31) {
            int nb = buf ^ 1;
            As[nb][lk + 0][lrow] = ra.x; As[nb][lk + 1][lrow] = ra.y;
            As[nb][lk + 2][lrow] = ra.z; As[nb][lk + 3][lrow] = ra.w;
            Bs[nb][lk + 0][lrow] = rb.x; Bs[nb][lk + 1][lrow] = rb.y;
            Bs[nb][lk + 2][lrow] = rb.z; Bs[nb][lk + 3][lrow] = rb.w;
            __syncthreads();
            buf = nb;
        }
    }

    // tile sum for the global mean (off-diag counts twice: mirrored tile)
    float s = 0.0f;
#pragma unroll
    for (int i = 0; i < 8; ++i)
#pragma unroll
        for (int j = 0; j < 8; ++j) s += acc[i][j];
    if (bi != bj) s *= 2.0f;
    red[tid] = s;
    __syncthreads();
    for (int o = 128; o > 0; o >>= 1) {
        if (tid < o) red[tid] += red[tid + o];
        __syncthreads();
    }
    if (tid == 0) g_adjpart[b] = red[0];

    // store tile (bi,bj)
#pragma unroll
    for (int i = 0; i < 8; ++i) {
        int m = m0 + ty4 + (i < 4 ? i : 60 + i);
        float4 v0 = make_float4(acc[i][0], acc[i][1], acc[i][2], acc[i][3]);
        float4 v1 = make_float4(acc[i][4], acc[i][5], acc[i][6], acc[i][7]);
        *reinterpret_cast<float4*>(&g_ADJ[(size_t)m * NN + n0 + tx4]) = v0;
        *reinterpret_cast<float4*>(&g_ADJ[(size_t)m * NN + n0 + tx4 + 64]) = v1;
    }
    // mirror to (bj,bi)
    if (bi != bj) {
#pragma unroll
        for (int j = 0; j < 8; ++j) {
            int n = n0 + tx4 + (j < 4 ? j : 60 + j);
            float4 u0 = make_float4(acc[0][j], acc[1][j], acc[2][j], acc[3][j]);
            float4 u1 = make_float4(acc[4][j], acc[5][j], acc[6][j], acc[7][j]);
            *reinterpret_cast<float4*>(&g_ADJ[(size_t)n * NN + m0 + ty4]) = u0;
            *reinterpret_cast<float4*>(&g_ADJ[(size_t)n * NN + m0 + ty4 + 64]) = u1;
        }
    }
}

__global__ void reduce_adjsum()
{
    __shared__ float red[512];
    int t = threadIdx.x;  // 512
    float v = g_adjpart[t];
    if (t < NTB - 512) v += g_adjpart[512 + t];
    red[t] = v;
    __syncthreads();
    for (int o = 256; o > 0; o >>= 1) {
        if (t < o) red[t] += red[t + o];
        __syncthreads();
    }
    if (t == 0) g_mean = red[0] * (1.0f / ((float)NN * (float)NN));
}

// -------- Yp[kz] = (ADJ > mean)[:, kz-slab] @ X[kz-slab]  (64m x 256n tiles) --
__global__ __launch_bounds__(256, 2) void gemm_thresh(const float* __restrict__ X)
{
    const float mean = g_mean;
    const int m0 = blockIdx.x * 64;
    const int kz = blockIdx.y;
    const int kbase = kz * 1024;

    __shared__ __align__(16) float As[2][8][64];
    __shared__ __align__(16) float Bs[2][8][256];

    const int tid = threadIdx.x;
    const int tx4 = (tid & 31) * 4;   // n fragment base
    const int ty4 = (tid >> 5) * 4;   // m fragment base
    const int alrow = tid >> 1, alk = (tid & 1) * 4;   // A loader (tid < 128)
    const int brow = tid >> 5, bcol = (tid & 31) * 8;  // B loader (all)

    const float* pA = g_ADJ + (size_t)(m0 + alrow) * NN + kbase + alk;
    const float* pB = X + (kbase + brow) * 256 + bcol;

    float acc[8][8] = {};
    float4 ra = make_float4(0, 0, 0, 0), rb0, rb1;
    if (tid < 128) ra = *reinterpret_cast<const float4*>(pA);
    rb0 = *reinterpret_cast<const float4*>(pB);
    rb1 = *reinterpret_cast<const float4*>(pB + 4);

    int buf = 0;
    if (tid < 128) {
        As[0][alk + 0][alrow] = ra.x > mean ? 1.0f : 0.0f;
        As[0][alk + 1][alrow] = ra.y > mean ? 1.0f : 0.0f;
        As[0][alk + 2][alrow] = ra.z > mean ? 1.0f : 0.0f;
        As[0][alk + 3][alrow] = ra.w > mean ? 1.0f : 0.0f;
    }
    *reinterpret_cast<float4*>(&Bs[0][brow][bcol]) = rb0;
    *reinterpret_cast<float4*>(&Bs[0][brow][bcol + 4]) = rb1;
    __syncthreads();

    for (int c = 0; c < 128; ++c) {
        if (c < 127) {
            if (tid < 128) ra = *reinterpret_cast<const float4*>(pA + (c + 1) * 8);
            rb0 = *reinterpret_cast<const float4*>(pB + (size_t)(c + 1) * 2048);
            rb1 = *reinterpret_cast<const float4*>(pB + (size_t)(c + 1) * 2048 + 4);
        }
#pragma unroll
        for (int kk = 0; kk < 8; ++kk) {
            float4 a0 = *reinterpret_cast<const float4*>(&As[buf][kk][ty4]);
            float4 a1 = *reinterpret_cast<const float4*>(&As[buf][kk][ty4 + 32]);
            float4 b0 = *reinterpret_cast<const float4*>(&Bs[buf][kk][tx4]);
            float4 b1 = *reinterpret_cast<const float4*>(&Bs[buf][kk][tx4 + 128]);
            float a[8] = {a0.x, a0.y, a0.z, a0.w, a1.x, a1.y, a1.z, a1.w};
            float bb[8] = {b0.x, b0.y, b0.z, b0.w, b1.x, b1.y, b1.z, b1.w};
#pragma unroll
            for (int i = 0; i < 8; ++i)
#pragma unroll
                for (int j = 0; j < 8; ++j) acc[i][j] += a[i] * bb[j];
        }
        if (c < 127) {
            int nb = buf ^ 1;
            if (tid < 128) {
                As[nb][alk + 0][alrow] = ra.x > mean ? 1.0f : 0.0f;
                As[nb][alk + 1][alrow] = ra.y > mean ? 1.0f : 0.0f;
                As[nb][alk + 2][alrow] = ra.z > mean ? 1.0f : 0.0f;
                As[nb][alk + 3][alrow] = ra.w > mean ? 1.0f : 0.0f;
            }
            *reinterpret_cast<float4*>(&Bs[nb][brow][bcol]) = rb0;
            *reinterpret_cast<float4*>(&Bs[nb][brow][bcol + 4]) = rb1;
            __syncthreads();
            buf = nb;
        }
    }

    float* Yp = g_Yp + (size_t)kz * ND;
#pragma unroll
    for (int i = 0; i < 8; ++i) {
        int m = m0 + ty4 + (i < 4 ? i : 28 + i);
        float4 v0 = make_float4(acc[i][0], acc[i][1], acc[i][2], acc[i][3]);
        float4 v1 = make_float4(acc[i][4], acc[i][5], acc[i][6], acc[i][7]);
        *reinterpret_cast<float4*>(&Yp[m * 256 + tx4]) = v0;
        *reinterpret_cast<float4*>(&Yp[m * 256 + tx4 + 128]) = v1;
    }
}

// Y = sum_k Yp[k] + X   (deterministic fixed-order combine; identity term E=1)
__global__ void combine_Y(const float* __restrict__ X, float* __restrict__ Y)
{
    const float4* x4 = reinterpret_cast<const float4*>(X);
    const float4* p4 = reinterpret_cast<const float4*>(g_Yp);
    float4* y4 = reinterpret_cast<float4*>(Y);
    const int n4 = ND / 4;
    int stride = gridDim.x * blockDim.x;
    for (int i = blockIdx.x * blockDim.x + threadIdx.x; i < n4; i += stride) {
        float4 x = x4[i];
        float4 a = p4[i];
        float4 b = p4[i + n4];
        float4 c = p4[i + 2 * n4];
        float4 d = p4[i + 3 * n4];
        float4 r;
        r.x = x.x + ((a.x + b.x) + (c.x + d.x));
        r.y = x.y + ((a.y + b.y) + (c.y + d.y));
        r.z = x.z + ((a.z + b.z) + (c.z + d.z));
        r.w = x.w + ((a.w + b.w) + (c.w + d.w));
        y4[i] = r;
    }
}

// ---------------- BatchNorm stats (deterministic 2-stage) -------------------
__global__ void colstats(const float* __restrict__ H)
{
    int t = threadIdx.x;
    int r0 = blockIdx.x * 128;
    float s = 0.0f, q = 0.0f;
    for (int r = r0; r < r0 + 128; ++r) {
        float v = H[r * 256 + t];
        s += v;
        q += v * v;
    }
    g_colpart[blockIdx.x * 512 + t] = s;
    g_colpart[blockIdx.x * 512 + 256 + t] = q;
}

__global__ void finalize_stats(const float* __restrict__ gamma,
                               const float* __restrict__ beta)
{
    int t = threadIdx.x;
    float s = 0.0f, q = 0.0f;
    for (int b = 0; b < 32; ++b) {
        s += g_colpart[b * 512 + t];
        q += g_colpart[b * 512 + 256 + t];
    }
    float mu = s * (1.0f / (float)NN);
    float var = q * (1.0f / (float)NN) - mu * mu;
    float rstd = rsqrtf(var + 1e-5f);
    float sc = gamma[t] * rstd;
    g_bnscale[t] = sc;
    g_bnshift[t] = beta[t] - mu * sc;
}

__global__ void bn_relu(float* __restrict__ H)
{
    int stride = gridDim.x * blockDim.x;
    for (int i = blockIdx.x * blockDim.x + threadIdx.x; i < ND; i += stride) {
        int c = i & 255;
        float h = H[i] * g_bnscale[c] + g_bnshift[c];
        H[i] = fmaxf(h, 0.0f);
    }
}

// ---------------- init / scale / MSE ----------------------------------------
__global__ void init_X_ACC(const float* __restrict__ Xin)
{
    int stride = gridDim.x * blockDim.x;
    for (int i = blockIdx.x * blockDim.x + threadIdx.x; i < ND; i += stride) {
        g_X[i] = Xin[i];
        g_ACC[i] = 0.0f;
    }
}

__global__ void scale_store(int branch)
{
    int stride = gridDim.x * blockDim.x;
    for (int i = blockIdx.x * blockDim.x + threadIdx.x; i < ND; i += stride)
        g_G[branch][i] = g_ACC[i] * (1.0f / 3.0f);
}

__global__ void mse_partial()
{
    int t = threadIdx.x, b = blockIdx.x;
    float s0 = 0.0f, s1 = 0.0f, s2 = 0.0f;
    for (int i = b * 256 + t; i < ND; i += 256 * 256) {
        float ga = g_G[3][i];
        float d0 = g_G[0][i] - ga;
        float d1 = g_G[1][i] - ga;
        float d2 = g_G[2][i] - ga;
        s0 += d0 * d0;
        s1 += d1 * d1;
        s2 += d2 * d2;
    }
    __shared__ float r[3][256];
    r[0][t] = s0; r[1][t] = s1; r[2][t] = s2;
    __syncthreads();
    for (int o = 128; o > 0; o >>= 1) {
        if (t < o) {
            r[0][t] += r[0][t + o];
            r[1][t] += r[1][t + o];
            r[2][t] += r[2][t + o];
        }
        __syncthreads();
    }
    if (t == 0) {
        g_msepart[b * 3 + 0] = r[0][0];
        g_msepart[b * 3 + 1] = r[1][0];
        g_msepart[b * 3 + 2] = r[2][0];
    }
}

__global__ void mse_final(float* __restrict__ out)
{
    int t = threadIdx.x;
    __shared__ float r[256];
    for (int v = 0; v < 3; ++v) {
        r[t] = g_msepart[t * 3 + v];
        __syncthreads();
        for (int o = 128; o > 0; o >>= 1) {
            if (t < o) r[t] += r[t + o];
            __syncthreads();
        }
        if (t == 0) out[v] = r[0] * (1.0f / (float)ND);
        __syncthreads();
    }
}

// ---------------- host driver ------------------------------------------------
struct Scratch {
    float *X, *H1, *H2, *Y, *Hm, *ACC;
};

static void run_gin(const Scratch& p, const float* Xin,
                    const float* aW, const float* ab,
                    const float* mW, const float* mb, const float* mbn,
                    int branch)
{
    const dim3 g_small(4, 64);
    init_X_ACC<<<1024, 256>>>(Xin);
    for (int l = 0; l < LL; ++l) {
        // adjacency learner
        gemm_k256<0><<<g_small, 256>>>(p.X, aW, ab, p.H1, nullptr);
        gemm_k256<0><<<g_small, 256>>>(p.H1, aW + 65536, ab + 256, p.H2, nullptr);
        gemm_nt_sym<<<NTB, 256>>>(p.H2);
        reduce_adjsum<<<1, 512>>>();
        // aggregate (oh + I) @ X   (split-K partials + combine)
        gemm_thresh<<<dim3(64, 4), 256>>>(p.X);
        combine_Y<<<512, 256>>>(p.X, p.Y);
        // GIN MLP
        const float* W0 = mW + (size_t)(l * 2) * 65536;
        const float* W1 = W0 + 65536;
        const float* b0 = mb + l * 2 * 256;
        const float* b1 = b0 + 256;
        const float* gamma = mbn + l * 2 * 256;
        const float* beta = gamma + 256;
        gemm_k256<1><<<g_small, 256>>>(p.Y, W0, b0, p.Hm, nullptr);
        colstats<<<32, 256>>>(p.Hm);
        finalize_stats<<<1, 256>>>(gamma, beta);
        bn_relu<<<1024, 256>>>(p.Hm);
        gemm_k256<2><<<g_small, 256>>>(p.Hm, W1, b1, p.X, p.ACC);
    }
    scale_store<<<1024, 256>>>(branch);
}

extern "C" void kernel_launch(void* const* d_in, const int* in_sizes, int n_in,
                              void* d_out, int out_size)
{
    const float* QV = (const float*)d_in[0];
    const float* Q  = (const float*)d_in[1];
    const float* V  = (const float*)d_in[2];
    const float* A  = (const float*)d_in[3];
    const float* adjW_qv  = (const float*)d_in[4];
    const float* adjb_qv  = (const float*)d_in[5];
    const float* mlpW_qv  = (const float*)d_in[6];
    const float* mlpb_qv  = (const float*)d_in[7];
    const float* mlpbn_qv = (const float*)d_in[8];
    const float* adjW_t   = (const float*)d_in[9];
    const float* adjb_t   = (const float*)d_in[10];
    const float* mlpW_t   = (const float*)d_in[11];
    const float* mlpb_t   = (const float*)d_in[12];
    const float* mlpbn_t  = (const float*)d_in[13];
    const float* adjW_v   = (const float*)d_in[14];
    const float* adjb_v   = (const float*)d_in[15];
    const float* mlpW_v   = (const float*)d_in[16];
    const float* mlpb_v   = (const float*)d_in[17];
    const float* mlpbn_v  = (const float*)d_in[18];

    Scratch p;
    cudaGetSymbolAddress((void**)&p.X, g_X);
    cudaGetSymbolAddress((void**)&p.H1, g_H1);
    cudaGetSymbolAddress((void**)&p.H2, g_H2);
    cudaGetSymbolAddress((void**)&p.Y, g_Y);
    cudaGetSymbolAddress((void**)&p.Hm, g_Hm);
    cudaGetSymbolAddress((void**)&p.ACC, g_ACC);

    run_gin(p, QV, adjW_qv, adjb_qv, mlpW_qv, mlpb_qv, mlpbn_qv, 0);
    run_gin(p, Q,  adjW_t,  adjb_t,  mlpW_t,  mlpb_t,  mlpbn_t,  1);
    run_gin(p, V,  adjW_v,  adjb_v,  mlpW_v,  mlpb_v,  mlpbn_v,  2);
    run_gin(p, A,  adjW_t,  adjb_t,  mlpW_t,  mlpb_t,  mlpbn_t,  3);

    mse_partial<<<256, 256>>>();
    mse_final<<<1, 256>>>((float*)d_out);
}

// round 4
// speedup vs baseline: 3.4071x; 1.5758x over previous
#include <cuda_runtime.h>
#include <cuda_bf16.h>
#include <math.h>
#include <stdint.h>

#define NN 4096
#define DD 256
#define LL 3
#define ND (NN * DD)
#define NTB 528   // 32*33/2 upper-triangular 128x128 tiles
#define KZ 8      // split-K slabs for thresh

// ---------------- scratch (device globals; no allocation allowed) ----------
__device__ float g_X[ND];
__device__ float g_H1[ND];
__device__ float g_Y[ND];
__device__ float g_Hm[ND];
__device__ float g_ACC[ND];
__device__ float g_G[4][ND];
__device__ float g_ADJ[NN * NN];              // 64 MB fp32
__device__ float g_Yp[KZ * ND];               // split-K partials (32 MB)
__device__ __nv_bfloat16 g_Hh[ND];            // adj-learner h, bf16 hi
__device__ __nv_bfloat16 g_Hl[ND];            // adj-learner h, bf16 lo
__device__ __nv_bfloat16 g_Xth[ND];           // X^T bf16 hi [256,4096]
__device__ __nv_bfloat16 g_Xtl[ND];           // X^T bf16 lo [256,4096]
__device__ float g_adjpart[NTB];
__device__ float g_mean;
__device__ float g_colpart[32 * 512];
__device__ float g_bnscale[DD];
__device__ float g_bnshift[DD];
__device__ float g_msepart[256 * 3];

__device__ __forceinline__ float eluf(float x) {
    return x > 0.0f ? x : (expf(x) - 1.0f);
}

// =================== warp MMA helpers (sm_80-compatible) ====================
__device__ __forceinline__ uint32_t smem_u32(const void* p) {
    uint32_t a;
    asm("{ .reg .u64 t; cvta.to.shared.u64 t, %1; cvt.u32.u64 %0, t; }"
        : "=r"(a) : "l"(p));
    return a;
}

__device__ __forceinline__ void ldsm4(uint32_t (&r)[4], uint32_t addr) {
    asm volatile("ldmatrix.sync.aligned.m8n8.x4.shared.b16 {%0,%1,%2,%3}, [%4];"
                 : "=r"(r[0]), "=r"(r[1]), "=r"(r[2]), "=r"(r[3]) : "r"(addr));
}

__device__ __forceinline__ void mma16816(float (&d)[4], const uint32_t (&a)[4],
                                         uint32_t b0, uint32_t b1) {
    asm volatile(
        "mma.sync.aligned.m16n8k16.row.col.f32.bf16.bf16.f32 "
        "{%0,%1,%2,%3}, {%4,%5,%6,%7}, {%8,%9}, {%0,%1,%2,%3};"
        : "+f"(d[0]), "+f"(d[1]), "+f"(d[2]), "+f"(d[3])
        : "r"(a[0]), "r"(a[1]), "r"(a[2]), "r"(a[3]), "r"(b0), "r"(b1));
}

// 128B-row swizzle: tile rows of 64 bf16 (128 bytes)
__device__ __forceinline__ uint32_t swz(uint32_t row, uint32_t k) {
    uint32_t o = row * 128u + k * 2u;
    return o ^ ((o >> 3) & 0x70u);
}

// =================== ADJ = H@H^T via mma.sync (bf16 hi/lo split) ===========
#define ADJ_SMEM 67584   // max(4*16KB tiles, 128*132*4 transpose buffer)
__global__ __launch_bounds__(256, 1) void adj_mma(
    const __nv_bfloat16* __restrict__ Hh, const __nv_bfloat16* __restrict__ Hl)
{
    extern __shared__ __align__(16) char smem[];
    const uint32_t sb = smem_u32(smem);
    const int tid = threadIdx.x, wid = tid >> 5, lane = tid & 31;

    int b = blockIdx.x, bi = 0, rem = b;
    while (rem >= 32 - bi) { rem -= 32 - bi; ++bi; }
    const int bj = bi + rem;
    const bool diag = (bi == bj);
    const int m0 = bi * 128, n0 = bj * 128;
    const int wm = wid >> 2, wn = wid & 3;   // 2x4 warp grid, warp tile 64x32

    char* Ah = smem;
    char* Al = smem + 16384;
    char* Bh = diag ? Ah : smem + 32768;
    char* Bl = diag ? Al : smem + 49152;
    const uint32_t oAh = 0, oAl = 16384;
    const uint32_t oBh = diag ? 0u : 32768u, oBl = diag ? 16384u : 49152u;

    const int arow = lane & 15, akh = (lane >> 4) * 8;
    const int brow = ((lane >> 4) << 3) + (lane & 7), bkh = ((lane >> 3) & 1) * 8;

    float c[4][4][4] = {};

    for (int ch = 0; ch < 4; ++ch) {
        const int kb = ch * 64;
        __syncthreads();
#pragma unroll
        for (int t = 0; t < 4; ++t) {
            int idx = tid + t * 256;
            int r = idx >> 3, g = (idx & 7) * 8;
            *(uint4*)(Ah + swz(r, g)) = *(const uint4*)(Hh + (m0 + r) * 256 + kb + g);
            *(uint4*)(Al + swz(r, g)) = *(const uint4*)(Hl + (m0 + r) * 256 + kb + g);
            if (!diag) {
                *(uint4*)(Bh + swz(r, g)) = *(const uint4*)(Hh + (n0 + r) * 256 + kb + g);
                *(uint4*)(Bl + swz(r, g)) = *(const uint4*)(Hl + (n0 + r) * 256 + kb + g);
            }
        }
        __syncthreads();
#pragma unroll
        for (int s = 0; s < 4; ++s) {
            uint32_t ah[4][4], al[4][4];
#pragma unroll
            for (int mt = 0; mt < 4; ++mt) {
                ldsm4(ah[mt], sb + oAh + swz(wm * 64 + mt * 16 + arow, s * 16 + akh));
                ldsm4(al[mt], sb + oAl + swz(wm * 64 + mt * 16 + arow, s * 16 + akh));
            }
#pragma unroll
            for (int np = 0; np < 2; ++np) {
                uint32_t bh[4], bl[4];
                ldsm4(bh, sb + oBh + swz(wn * 32 + np * 16 + brow, s * 16 + bkh));
                ldsm4(bl, sb + oBl + swz(wn * 32 + np * 16 + brow, s * 16 + bkh));
#pragma unroll
                for (int mt = 0; mt < 4; ++mt) {
#pragma unroll
                    for (int j = 0; j < 2; ++j) {
                        mma16816(c[mt][np * 2 + j], ah[mt], bh[2 * j], bh[2 * j + 1]);
                        mma16816(c[mt][np * 2 + j], ah[mt], bl[2 * j], bl[2 * j + 1]);
                        mma16816(c[mt][np * 2 + j], al[mt], bh[2 * j], bh[2 * j + 1]);
                    }
                }
            }
        }
    }

    // epilogue: write tile + tile sum
    const int lr = lane >> 2, lc = (lane & 3) * 2;
    float tsum = 0.0f;
#pragma unroll
    for (int mt = 0; mt < 4; ++mt)
#pragma unroll
        for (int nt = 0; nt < 4; ++nt) {
            int m = m0 + wm * 64 + mt * 16 + lr;
            int n = n0 + wn * 32 + nt * 8 + lc;
            *(float2*)&g_ADJ[(size_t)m * NN + n] =
                make_float2(c[mt][nt][0], c[mt][nt][1]);
            *(float2*)&g_ADJ[(size_t)(m + 8) * NN + n] =
                make_float2(c[mt][nt][2], c[mt][nt][3]);
            tsum += (c[mt][nt][0] + c[mt][nt][1]) + (c[mt][nt][2] + c[mt][nt][3]);
        }
    for (int o = 16; o > 0; o >>= 1) tsum += __shfl_down_sync(0xFFFFFFFFu, tsum, o);
    __shared__ float ws[8];
    if (lane == 0) ws[wid] = tsum;
    __syncthreads();
    if (tid == 0) {
        float s = 0.0f;
        for (int w = 0; w < 8; ++w) s += ws[w];
        g_adjpart[b] = diag ? s : 2.0f * s;
    }

    // mirror via smem transpose (coalesced write of tile^T)
    if (!diag) {
        float* T = reinterpret_cast<float*>(smem);  // [128 n][132]
        __syncthreads();
#pragma unroll
        for (int mt = 0; mt < 4; ++mt)
#pragma unroll
            for (int nt = 0; nt < 4; ++nt) {
                int ml = wm * 64 + mt * 16 + lr;
                int nl = wn * 32 + nt * 8 + lc;
                T[nl * 132 + ml] = c[mt][nt][0];
                T[(nl + 1) * 132 + ml] = c[mt][nt][1];
                T[nl * 132 + ml + 8] = c[mt][nt][2];
                T[(nl + 1) * 132 + ml + 8] = c[mt][nt][3];
            }
        __syncthreads();
        int n = tid >> 1, mh = (tid & 1) * 64;
        float4* dst = reinterpret_cast<float4*>(&g_ADJ[(size_t)(n0 + n) * NN + m0 + mh]);
        const float4* src = reinterpret_cast<const float4*>(T + n * 132 + mh);
#pragma unroll
        for (int q = 0; q < 16; ++q) dst[q] = src[q];
    }
}

__global__ void reduce_adjsum()
{
    __shared__ float red[512];
    int t = threadIdx.x;
    float v = g_adjpart[t];
    if (t < NTB - 512) v += g_adjpart[512 + t];
    red[t] = v;
    __syncthreads();
    for (int o = 256; o > 0; o >>= 1) {
        if (t < o) red[t] += red[t + o];
        __syncthreads();
    }
    if (t == 0) g_mean = red[0] * (1.0f / ((float)NN * (float)NN));
}

// ====== Yp[kz] = (ADJ > mean)[:, kz-slab] @ X[kz-slab] via mma.sync =========
#define THR_SMEM 81920   // A 16KB + Bh 32KB + Bl 32KB
__global__ __launch_bounds__(256, 1) void thresh_mma()
{
    extern __shared__ __align__(16) char smem[];
    const uint32_t sb = smem_u32(smem);
    const int tid = threadIdx.x, wid = tid >> 5, lane = tid & 31;
    const int m0 = blockIdx.x * 128;
    const int kz = blockIdx.y;
    const float mean = g_mean;
    const int wm = wid >> 2, wn = wid & 3;   // warp tile 64m x 64n

    char* At = smem;
    char* Bh = smem + 16384;
    char* Bl = smem + 49152;

    const int arow = lane & 15, akh = (lane >> 4) * 8;
    const int brow = ((lane >> 4) << 3) + (lane & 7), bkh = ((lane >> 3) & 1) * 8;

    float c[4][8][4] = {};

    for (int ch = 0; ch < 8; ++ch) {
        const int kb = kz * 512 + ch * 64;
        __syncthreads();
#pragma unroll
        for (int t = 0; t < 4; ++t) {
            int idx = tid + t * 256;
            int r = idx >> 3, g = (idx & 7) * 8;
            const float* p = g_ADJ + (size_t)(m0 + r) * NN + kb + g;
            float4 f0 = *(const float4*)p;
            float4 f1 = *(const float4*)(p + 4);
            uint4 w;
            w.x = (f0.x > mean ? 0x3F80u : 0u) | ((f0.y > mean ? 0x3F80u : 0u) << 16);
            w.y = (f0.z > mean ? 0x3F80u : 0u) | ((f0.w > mean ? 0x3F80u : 0u) << 16);
            w.z = (f1.x > mean ? 0x3F80u : 0u) | ((f1.y > mean ? 0x3F80u : 0u) << 16);
            w.w = (f1.z > mean ? 0x3F80u : 0u) | ((f1.w > mean ? 0x3F80u : 0u) << 16);
            *(uint4*)(At + swz(r, g)) = w;
        }
#pragma unroll
        for (int t = 0; t < 8; ++t) {
            int idx = tid + t * 256;
            int r = idx >> 3, g = (idx & 7) * 8;
            *(uint4*)(Bh + swz(r, g)) = *(const uint4*)(g_Xth + r * 4096 + kb + g);
            *(uint4*)(Bl + swz(r, g)) = *(const uint4*)(g_Xtl + r * 4096 + kb + g);
        }
        __syncthreads();
#pragma unroll
        for (int s = 0; s < 4; ++s) {
            uint32_t a[4][4];
#pragma unroll
            for (int mt = 0; mt < 4; ++mt)
                ldsm4(a[mt], sb + swz(wm * 64 + mt * 16 + arow, s * 16 + akh));
#pragma unroll
            for (int np = 0; np < 4; ++np) {
                uint32_t bh[4], bl[4];
                ldsm4(bh, sb + 16384 + swz(wn * 64 + np * 16 + brow, s * 16 + bkh));
                ldsm4(bl, sb + 49152 + swz(wn * 64 + np * 16 + brow, s * 16 + bkh));
#pragma unroll
                for (int mt = 0; mt < 4; ++mt) {
#pragma unroll
                    for (int j = 0; j < 2; ++j) {
                        mma16816(c[mt][np * 2 + j], a[mt], bh[2 * j], bh[2 * j + 1]);
                        mma16816(c[mt][np * 2 + j], a[mt], bl[2 * j], bl[2 * j + 1]);
                    }
                }
            }
        }
    }

    float* Yp = g_Yp + (size_t)kz * ND;
    const int lr = lane >> 2, lc = (lane & 3) * 2;
#pragma unroll
    for (int mt = 0; mt < 4; ++mt)
#pragma unroll
        for (int nt = 0; nt < 8; ++nt) {
            int m = m0 + wm * 64 + mt * 16 + lr;
            int n = wn * 64 + nt * 8 + lc;
            *(float2*)&Yp[m * 256 + n] = make_float2(c[mt][nt][0], c[mt][nt][1]);
            *(float2*)&Yp[(m + 8) * 256 + n] = make_float2(c[mt][nt][2], c[mt][nt][3]);
        }
}

// Y = sum_k Yp[k] + X (deterministic fixed order; E=1 identity term)
__global__ void combine_Y(const float* __restrict__ X, float* __restrict__ Y)
{
    const float4* x4 = reinterpret_cast<const float4*>(X);
    const float4* p4 = reinterpret_cast<const float4*>(g_Yp);
    float4* y4 = reinterpret_cast<float4*>(Y);
    const int n4 = ND / 4;
    int stride = gridDim.x * blockDim.x;
    for (int i = blockIdx.x * blockDim.x + threadIdx.x; i < n4; i += stride) {
        float4 r = x4[i];
#pragma unroll
        for (int k = 0; k < KZ; ++k) {
            float4 a = p4[i + k * n4];
            r.x += a.x; r.y += a.y; r.z += a.z; r.w += a.w;
        }
        y4[i] = r;
    }
}

// =============== small GEMM C[4096,256] = act(A @ W + b) ====================
// EPI 0: ELU f32  1: bias  2: bias + ACC += C  3: ELU -> bf16 hi/lo
template <int EPI>
__global__ __launch_bounds__(256, 2) void gemm_small(
    const float* __restrict__ A, const float* __restrict__ W,
    const float* __restrict__ bias, float* __restrict__ C,
    __nv_bfloat16* __restrict__ Ch, __nv_bfloat16* __restrict__ Cl,
    float* __restrict__ ACC)
{
    __shared__ __align__(16) float As[2][8][128];
    __shared__ __align__(16) float Bs[2][8][64];
    const int tid = threadIdx.x;
    const int tx = tid & 15, ty = tid >> 4;
    const int m0 = blockIdx.y * 128, n0 = blockIdx.x * 64;
    const int ar = tid >> 1, ak = (tid & 1) * 4;
    const int bk = tid >> 4, bn = (tid & 15) * 4;

    const float* pA = A + (m0 + ar) * 256 + ak;
    const float* pB = W + bk * 256 + n0 + bn;

    float acc[8][4] = {};
    float4 ra = *reinterpret_cast<const float4*>(pA);
    float4 rb = make_float4(0, 0, 0, 0);
    if (tid < 128) rb = *reinterpret_cast<const float4*>(pB);

    int buf = 0;
    As[0][ak + 0][ar] = ra.x; As[0][ak + 1][ar] = ra.y;
    As[0][ak + 2][ar] = ra.z; As[0][ak + 3][ar] = ra.w;
    if (tid < 128) *reinterpret_cast<float4*>(&Bs[0][bk][bn]) = rb;
    __syncthreads();

    for (int c = 0; c < 32; ++c) {
        if (c < 31) {
            ra = *reinterpret_cast<const float4*>(pA + (c + 1) * 8);
            if (tid < 128)
                rb = *reinterpret_cast<const float4*>(pB + (size_t)(c + 1) * 2048);
        }
#pragma unroll
        for (int kk = 0; kk < 8; ++kk) {
            float4 a0 = *reinterpret_cast<const float4*>(&As[buf][kk][ty * 8]);
            float4 a1 = *reinterpret_cast<const float4*>(&As[buf][kk][ty * 8 + 4]);
            float4 b = *reinterpret_cast<const float4*>(&Bs[buf][kk][tx * 4]);
            float a[8] = {a0.x, a0.y, a0.z, a0.w, a1.x, a1.y, a1.z, a1.w};
            float bb[4] = {b.x, b.y, b.z, b.w};
#pragma unroll
            for (int i = 0; i < 8; ++i)
#pragma unroll
                for (int j = 0; j < 4; ++j) acc[i][j] += a[i] * bb[j];
        }
        if (c < 31) {
            int nb = buf ^ 1;
            As[nb][ak + 0][ar] = ra.x; As[nb][ak + 1][ar] = ra.y;
            As[nb][ak + 2][ar] = ra.z; As[nb][ak + 3][ar] = ra.w;
            if (tid < 128) *reinterpret_cast<float4*>(&Bs[nb][bk][bn]) = rb;
            __syncthreads();
            buf = nb;
        }
    }

    float4 bv = *reinterpret_cast<const float4*>(&bias[n0 + tx * 4]);
    float bvv[4] = {bv.x, bv.y, bv.z, bv.w};
#pragma unroll
    for (int i = 0; i < 8; ++i) {
        const int m = m0 + ty * 8 + i;
        const int n = n0 + tx * 4;
        float cv[4];
#pragma unroll
        for (int j = 0; j < 4; ++j) {
            float v = acc[i][j] + bvv[j];
            if (EPI == 0 || EPI == 3) v = eluf(v);
            cv[j] = v;
        }
        if (EPI == 3) {
#pragma unroll
            for (int j = 0; j < 4; ++j) {
                __nv_bfloat16 h = __float2bfloat16(cv[j]);
                __nv_bfloat16 l = __float2bfloat16(cv[j] - __bfloat162float(h));
                Ch[m * 256 + n + j] = h;
                Cl[m * 256 + n + j] = l;
            }
        } else {
            *reinterpret_cast<float4*>(&C[m * 256 + n]) =
                make_float4(cv[0], cv[1], cv[2], cv[3]);
            if (EPI == 2) {
                float4 old = *reinterpret_cast<const float4*>(&ACC[m * 256 + n]);
                *reinterpret_cast<float4*>(&ACC[m * 256 + n]) =
                    make_float4(old.x + cv[0], old.y + cv[1],
                                old.z + cv[2], old.w + cv[3]);
            }
        }
    }
}

// =============== X transpose + bf16 split: [4096,256] -> [256,4096] ========
__global__ void xt_split(const float* __restrict__ X)
{
    __shared__ float t[32][33];
    const int r0 = blockIdx.x * 32, c0 = blockIdx.y * 32;
    const int x = threadIdx.x, y = threadIdx.y;
    for (int i = 0; i < 32; i += 8)
        t[y + i][x] = X[(r0 + y + i) * 256 + c0 + x];
    __syncthreads();
    for (int i = 0; i < 32; i += 8) {
        float v = t[x][y + i];
        __nv_bfloat16 h = __float2bfloat16(v);
        __nv_bfloat16 l = __float2bfloat16(v - __bfloat162float(h));
        g_Xth[(c0 + y + i) * 4096 + r0 + x] = h;
        g_Xtl[(c0 + y + i) * 4096 + r0 + x] = l;
    }
}

// ---------------- BatchNorm stats (deterministic 2-stage) -------------------
__global__ void colstats(const float* __restrict__ H)
{
    int t = threadIdx.x;
    int r0 = blockIdx.x * 128;
    float s = 0.0f, q = 0.0f;
    for (int r = r0; r < r0 + 128; ++r) {
        float v = H[r * 256 + t];
        s += v;
        q += v * v;
    }
    g_colpart[blockIdx.x * 512 + t] = s;
    g_colpart[blockIdx.x * 512 + 256 + t] = q;
}

__global__ void finalize_stats(const float* __restrict__ gamma,
                               const float* __restrict__ beta)
{
    int t = threadIdx.x;
    float s = 0.0f, q = 0.0f;
    for (int b = 0; b < 32; ++b) {
        s += g_colpart[b * 512 + t];
        q += g_colpart[b * 512 + 256 + t];
    }
    float mu = s * (1.0f / (float)NN);
    float var = q * (1.0f / (float)NN) - mu * mu;
    float rstd = rsqrtf(var + 1e-5f);
    float sc = gamma[t] * rstd;
    g_bnscale[t] = sc;
    g_bnshift[t] = beta[t] - mu * sc;
}

__global__ void bn_relu(float* __restrict__ H)
{
    int stride = gridDim.x * blockDim.x;
    for (int i = blockIdx.x * blockDim.x + threadIdx.x; i < ND; i += stride) {
        int c = i & 255;
        float h = H[i] * g_bnscale[c] + g_bnshift[c];
        H[i] = fmaxf(h, 0.0f);
    }
}

// ---------------- init / scale / MSE ----------------------------------------
__global__ void init_X_ACC(const float* __restrict__ Xin)
{
    int stride = gridDim.x * blockDim.x;
    for (int i = blockIdx.x * blockDim.x + threadIdx.x; i < ND; i += stride) {
        g_X[i] = Xin[i];
        g_ACC[i] = 0.0f;
    }
}

__global__ void scale_store(int branch)
{
    int stride = gridDim.x * blockDim.x;
    for (int i = blockIdx.x * blockDim.x + threadIdx.x; i < ND; i += stride)
        g_G[branch][i] = g_ACC[i] * (1.0f / 3.0f);
}

__global__ void mse_partial()
{
    int t = threadIdx.x, b = blockIdx.x;
    float s0 = 0.0f, s1 = 0.0f, s2 = 0.0f;
    for (int i = b * 256 + t; i < ND; i += 256 * 256) {
        float ga = g_G[3][i];
        float d0 = g_G[0][i] - ga;
        float d1 = g_G[1][i] - ga;
        float d2 = g_G[2][i] - ga;
        s0 += d0 * d0;
        s1 += d1 * d1;
        s2 += d2 * d2;
    }
    __shared__ float r[3][256];
    r[0][t] = s0; r[1][t] = s1; r[2][t] = s2;
    __syncthreads();
    for (int o = 128; o > 0; o >>= 1) {
        if (t < o) {
            r[0][t] += r[0][t + o];
            r[1][t] += r[1][t + o];
            r[2][t] += r[2][t + o];
        }
        __syncthreads();
    }
    if (t == 0) {
        g_msepart[b * 3 + 0] = r[0][0];
        g_msepart[b * 3 + 1] = r[1][0];
        g_msepart[b * 3 + 2] = r[2][0];
    }
}

__global__ void mse_final(float* __restrict__ out)
{
    int t = threadIdx.x;
    __shared__ float r[256];
    for (int v = 0; v < 3; ++v) {
        r[t] = g_msepart[t * 3 + v];
        __syncthreads();
        for (int o = 128; o > 0; o >>= 1) {
            if (t < o) r[t] += r[t + o];
            __syncthreads();
        }
        if (t == 0) out[v] = r[0] * (1.0f / (float)ND);
        __syncthreads();
    }
}

// ---------------- host driver ------------------------------------------------
struct Scratch {
    float *X, *H1, *Y, *Hm, *ACC;
    __nv_bfloat16 *Hh, *Hl;
};

static void run_gin(const Scratch& p, const float* Xin,
                    const float* aW, const float* ab,
                    const float* mW, const float* mb, const float* mbn,
                    int branch)
{
    const dim3 g_small(4, 32);
    init_X_ACC<<<1024, 256>>>(Xin);
    for (int l = 0; l < LL; ++l) {
        // adjacency learner (2 small GEMMs, second emits bf16 hi/lo)
        gemm_small<0><<<g_small, 256>>>(p.X, aW, ab, p.H1, nullptr, nullptr, nullptr);
        gemm_small<3><<<g_small, 256>>>(p.H1, aW + 65536, ab + 256,
                                        nullptr, p.Hh, p.Hl, nullptr);
        adj_mma<<<NTB, 256, ADJ_SMEM>>>(p.Hh, p.Hl);
        reduce_adjsum<<<1, 512>>>();
        // aggregate (oh + I) @ X
        xt_split<<<dim3(128, 8), dim3(32, 8)>>>(p.X);
        thresh_mma<<<dim3(32, KZ), 256, THR_SMEM>>>();
        combine_Y<<<512, 256>>>(p.X, p.Y);
        // GIN MLP
        const float* W0 = mW + (size_t)(l * 2) * 65536;
        const float* W1 = W0 + 65536;
        const float* b0 = mb + l * 2 * 256;
        const float* b1 = b0 + 256;
        const float* gamma = mbn + l * 2 * 256;
        const float* beta = gamma + 256;
        gemm_small<1><<<g_small, 256>>>(p.Y, W0, b0, p.Hm, nullptr, nullptr, nullptr);
        colstats<<<32, 256>>>(p.Hm);
        finalize_stats<<<1, 256>>>(gamma, beta);
        bn_relu<<<1024, 256>>>(p.Hm);
        gemm_small<2><<<g_small, 256>>>(p.Hm, W1, b1, p.X, nullptr, nullptr, p.ACC);
    }
    scale_store<<<1024, 256>>>(branch);
}

extern "C" void kernel_launch(void* const* d_in, const int* in_sizes, int n_in,
                              void* d_out, int out_size)
{
    const float* QV = (const float*)d_in[0];
    const float* Q  = (const float*)d_in[1];
    const float* V  = (const float*)d_in[2];
    const float* A  = (const float*)d_in[3];
    const float* adjW_qv  = (const float*)d_in[4];
    const float* adjb_qv  = (const float*)d_in[5];
    const float* mlpW_qv  = (const float*)d_in[6];
    const float* mlpb_qv  = (const float*)d_in[7];
    const float* mlpbn_qv = (const float*)d_in[8];
    const float* adjW_t   = (const float*)d_in[9];
    const float* adjb_t   = (const float*)d_in[10];
    const float* mlpW_t   = (const float*)d_in[11];
    const float* mlpb_t   = (const float*)d_in[12];
    const float* mlpbn_t  = (const float*)d_in[13];
    const float* adjW_v   = (const float*)d_in[14];
    const float* adjb_v   = (const float*)d_in[15];
    const float* mlpW_v   = (const float*)d_in[16];
    const float* mlpb_v   = (const float*)d_in[17];
    const float* mlpbn_v  = (const float*)d_in[18];

    cudaFuncSetAttribute(adj_mma, cudaFuncAttributeMaxDynamicSharedMemorySize,
                         ADJ_SMEM);
    cudaFuncSetAttribute(thresh_mma, cudaFuncAttributeMaxDynamicSharedMemorySize,
                         THR_SMEM);

    Scratch p;
    cudaGetSymbolAddress((void**)&p.X, g_X);
    cudaGetSymbolAddress((void**)&p.H1, g_H1);
    cudaGetSymbolAddress((void**)&p.Y, g_Y);
    cudaGetSymbolAddress((void**)&p.Hm, g_Hm);
    cudaGetSymbolAddress((void**)&p.ACC, g_ACC);
    cudaGetSymbolAddress((void**)&p.Hh, g_Hh);
    cudaGetSymbolAddress((void**)&p.Hl, g_Hl);

    run_gin(p, QV, adjW_qv, adjb_qv, mlpW_qv, mlpb_qv, mlpbn_qv, 0);
    run_gin(p, Q,  adjW_t,  adjb_t,  mlpW_t,  mlpb_t,  mlpbn_t,  1);
    run_gin(p, V,  adjW_v,  adjb_v,  mlpW_v,  mlpb_v,  mlpbn_v,  2);
    run_gin(p, A,  adjW_t,  adjb_t,  mlpW_t,  mlpb_t,  mlpbn_t,  3);

    mse_partial<<<256, 256>>>();
    mse_final<<<1, 256>>>((float*)d_out);
}

// round 5
// speedup vs baseline: 5.5690x; 1.6345x over previous
#include <cuda_runtime.h>
#include <cuda_bf16.h>
#include <math.h>
#include <stdint.h>

#define NN 4096
#define DD 256
#define LL 3
#define ND (NN * DD)
#define NTB 528   // 32*33/2 upper-triangular 128x128 tiles
#define KZ 8      // split-K slabs for thresh

// ---------------- scratch (device globals; no allocation allowed) ----------
__device__ float g_X[ND];
__device__ float g_H1[ND];
__device__ float g_Y[ND];
__device__ float g_Hm[ND];
__device__ float g_ACC[ND];
__device__ float g_G[4][ND];
__device__ float g_ADJ[NN * NN];              // 64 MB fp32
__device__ float g_Yp[KZ * ND];               // split-K partials (32 MB)
__device__ __nv_bfloat16 g_Hh[ND];
__device__ __nv_bfloat16 g_Hl[ND];
__device__ __nv_bfloat16 g_Xth[ND];           // X^T bf16 hi [256,4096]
__device__ __nv_bfloat16 g_Xtl[ND];           // X^T bf16 lo [256,4096]
__device__ __nv_bfloat16 g_Wth[8 * DD * DD];  // W^T hi per branch (8 mats)
__device__ __nv_bfloat16 g_Wtl[8 * DD * DD];  // W^T lo
__device__ float g_adjpart[NTB];
__device__ float g_mean;
__device__ float g_colpart[32 * 512];
__device__ float g_bnscale[DD];
__device__ float g_bnshift[DD];
__device__ float g_msepart[256 * 3];

__device__ __forceinline__ float eluf(float x) {
    return x > 0.0f ? x : (expf(x) - 1.0f);
}

// =================== warp MMA / async helpers ================================
__device__ __forceinline__ uint32_t smem_u32(const void* p) {
    uint32_t a;
    asm("{ .reg .u64 t; cvta.to.shared.u64 t, %1; cvt.u32.u64 %0, t; }"
        : "=r"(a) : "l"(p));
    return a;
}
__device__ __forceinline__ void ldsm4(uint32_t (&r)[4], uint32_t addr) {
    asm volatile("ldmatrix.sync.aligned.m8n8.x4.shared.b16 {%0,%1,%2,%3}, [%4];"
                 : "=r"(r[0]), "=r"(r[1]), "=r"(r[2]), "=r"(r[3]) : "r"(addr));
}
__device__ __forceinline__ void mma16816(float (&d)[4], const uint32_t (&a)[4],
                                         uint32_t b0, uint32_t b1) {
    asm volatile(
        "mma.sync.aligned.m16n8k16.row.col.f32.bf16.bf16.f32 "
        "{%0,%1,%2,%3}, {%4,%5,%6,%7}, {%8,%9}, {%0,%1,%2,%3};"
        : "+f"(d[0]), "+f"(d[1]), "+f"(d[2]), "+f"(d[3])
        : "r"(a[0]), "r"(a[1]), "r"(a[2]), "r"(a[3]), "r"(b0), "r"(b1));
}
__device__ __forceinline__ void cp16(uint32_t dst, const void* src) {
    asm volatile("cp.async.ca.shared.global [%0], [%1], 16;" :: "r"(dst), "l"(src));
}
#define CP_COMMIT() asm volatile("cp.async.commit_group;" ::: "memory")
#define CP_WAIT0()  asm volatile("cp.async.wait_group 0;" ::: "memory")

// 128B-row swizzle: tile rows of 64 bf16 (128 bytes)
__device__ __forceinline__ uint32_t swz(uint32_t row, uint32_t k) {
    uint32_t o = row * 128u + k * 2u;
    return o ^ ((o >> 3) & 0x70u);
}
__device__ __forceinline__ uint32_t bf2pack(float a, float b) {
    __nv_bfloat162 t = __floats2bfloat162_rn(a, b);
    return *reinterpret_cast<uint32_t*>(&t);
}

// =================== ADJ = H@H^T via mma.sync + cp.async pipeline ===========
#define ADJ_SMEM 131072
__global__ __launch_bounds__(256, 1) void adj_mma(
    const __nv_bfloat16* __restrict__ Hh, const __nv_bfloat16* __restrict__ Hl)
{
    extern __shared__ __align__(16) char smem[];
    const uint32_t sb = smem_u32(smem);
    const int tid = threadIdx.x, wid = tid >> 5, lane = tid & 31;

    int b = blockIdx.x, bi = 0, rem = b;
    while (rem >= 32 - bi) { rem -= 32 - bi; ++bi; }
    const int bj = bi + rem;
    const bool diag = (bi == bj);
    const int m0 = bi * 128, n0 = bj * 128;
    const int wm = wid >> 2, wn = wid & 3;   // 2x4 warp grid, warp tile 64x32

    const uint32_t oAh = 0, oAl = 32768;
    const uint32_t oBh = diag ? 0u : 65536u, oBl = diag ? 32768u : 98304u;

    const int arow = lane & 15, akh = (lane >> 4) * 8;
    const int brow = ((lane >> 4) << 3) + (lane & 7), bkh = ((lane >> 3) & 1) * 8;

    auto issue = [&](int ch, int buf) {
        const int kb = ch * 64;
        const uint32_t bo = buf * 16384;
#pragma unroll
        for (int t = 0; t < 4; ++t) {
            int idx = tid + t * 256;
            int r = idx >> 3, g = (idx & 7) * 8;
            uint32_t so = swz(r, g);
            cp16(sb + oAh + bo + so, Hh + (m0 + r) * 256 + kb + g);
            cp16(sb + oAl + bo + so, Hl + (m0 + r) * 256 + kb + g);
            if (!diag) {
                cp16(sb + oBh + bo + so, Hh + (n0 + r) * 256 + kb + g);
                cp16(sb + oBl + bo + so, Hl + (n0 + r) * 256 + kb + g);
            }
        }
    };

    float c[4][4][4] = {};
    issue(0, 0);
    CP_COMMIT();
    int buf = 0;

    for (int ch = 0; ch < 4; ++ch) {
        CP_WAIT0();
        __syncthreads();
        if (ch < 3) { issue(ch + 1, buf ^ 1); CP_COMMIT(); }
        const uint32_t bo = buf * 16384;
#pragma unroll
        for (int s = 0; s < 4; ++s) {
            uint32_t ah[4][4], al[4][4];
#pragma unroll
            for (int mt = 0; mt < 4; ++mt) {
                ldsm4(ah[mt], sb + oAh + bo + swz(wm * 64 + mt * 16 + arow, s * 16 + akh));
                ldsm4(al[mt], sb + oAl + bo + swz(wm * 64 + mt * 16 + arow, s * 16 + akh));
            }
#pragma unroll
            for (int np = 0; np < 2; ++np) {
                uint32_t bh[4], bl[4];
                ldsm4(bh, sb + oBh + bo + swz(wn * 32 + np * 16 + brow, s * 16 + bkh));
                ldsm4(bl, sb + oBl + bo + swz(wn * 32 + np * 16 + brow, s * 16 + bkh));
#pragma unroll
                for (int mt = 0; mt < 4; ++mt) {
#pragma unroll
                    for (int j = 0; j < 2; ++j) {
                        mma16816(c[mt][np * 2 + j], ah[mt], bh[2 * j], bh[2 * j + 1]);
                        mma16816(c[mt][np * 2 + j], ah[mt], bl[2 * j], bl[2 * j + 1]);
                        mma16816(c[mt][np * 2 + j], al[mt], bh[2 * j], bh[2 * j + 1]);
                    }
                }
            }
        }
        buf ^= 1;
    }

    // epilogue: write tile + tile sum
    const int lr = lane >> 2, lc = (lane & 3) * 2;
    float tsum = 0.0f;
#pragma unroll
    for (int mt = 0; mt < 4; ++mt)
#pragma unroll
        for (int nt = 0; nt < 4; ++nt) {
            int m = m0 + wm * 64 + mt * 16 + lr;
            int n = n0 + wn * 32 + nt * 8 + lc;
            *(float2*)&g_ADJ[(size_t)m * NN + n] =
                make_float2(c[mt][nt][0], c[mt][nt][1]);
            *(float2*)&g_ADJ[(size_t)(m + 8) * NN + n] =
                make_float2(c[mt][nt][2], c[mt][nt][3]);
            tsum += (c[mt][nt][0] + c[mt][nt][1]) + (c[mt][nt][2] + c[mt][nt][3]);
        }
    for (int o = 16; o > 0; o >>= 1) tsum += __shfl_down_sync(0xFFFFFFFFu, tsum, o);
    __shared__ float ws[8];
    if (lane == 0) ws[wid] = tsum;
    __syncthreads();
    if (tid == 0) {
        float s = 0.0f;
        for (int w = 0; w < 8; ++w) s += ws[w];
        g_adjpart[b] = diag ? s : 2.0f * s;
    }

    // mirror via smem transpose (coalesced write of tile^T)
    if (!diag) {
        float* T = reinterpret_cast<float*>(smem);  // [128 n][132]
        __syncthreads();
#pragma unroll
        for (int mt = 0; mt < 4; ++mt)
#pragma unroll
            for (int nt = 0; nt < 4; ++nt) {
                int ml = wm * 64 + mt * 16 + lr;
                int nl = wn * 32 + nt * 8 + lc;
                T[nl * 132 + ml] = c[mt][nt][0];
                T[(nl + 1) * 132 + ml] = c[mt][nt][1];
                T[nl * 132 + ml + 8] = c[mt][nt][2];
                T[(nl + 1) * 132 + ml + 8] = c[mt][nt][3];
            }
        __syncthreads();
        int n = tid >> 1, mh = (tid & 1) * 64;
        float4* dst = reinterpret_cast<float4*>(&g_ADJ[(size_t)(n0 + n) * NN + m0 + mh]);
        const float4* src = reinterpret_cast<const float4*>(T + n * 132 + mh);
#pragma unroll
        for (int q = 0; q < 16; ++q) dst[q] = src[q];
    }
}

__global__ void reduce_adjsum()
{
    __shared__ float red[512];
    int t = threadIdx.x;
    float v = g_adjpart[t];
    if (t < NTB - 512) v += g_adjpart[512 + t];
    red[t] = v;
    __syncthreads();
    for (int o = 256; o > 0; o >>= 1) {
        if (t < o) red[t] += red[t + o];
        __syncthreads();
    }
    if (t == 0) g_mean = red[0] * (1.0f / ((float)NN * (float)NN));
}

// ====== Yp[kz] = (ADJ > mean)[:, kz-slab] @ X[kz-slab], cp.async B ==========
#define THR_SMEM 163840
__global__ __launch_bounds__(256, 1) void thresh_mma()
{
    extern __shared__ __align__(16) char smem[];
    const uint32_t sb = smem_u32(smem);
    const int tid = threadIdx.x, wid = tid >> 5, lane = tid & 31;
    const int m0 = blockIdx.x * 128;
    const int kz = blockIdx.y;
    const float mean = g_mean;
    const int wm = wid >> 2, wn = wid & 3;   // warp tile 64m x 64n

    const uint32_t oA = 0, oBh = 32768, oBl = 98304;

    const int arow = lane & 15, akh = (lane >> 4) * 8;
    const int brow = ((lane >> 4) << 3) + (lane & 7), bkh = ((lane >> 3) & 1) * 8;

    auto issueB = [&](int ch, int buf) {
        const int kb = kz * 512 + ch * 64;
        const uint32_t bo = buf * 32768;
#pragma unroll
        for (int t = 0; t < 8; ++t) {
            int idx = tid + t * 256;
            int r = idx >> 3, g = (idx & 7) * 8;
            uint32_t so = swz(r, g);
            cp16(sb + oBh + bo + so, g_Xth + r * 4096 + kb + g);
            cp16(sb + oBl + bo + so, g_Xtl + r * 4096 + kb + g);
        }
    };
    auto loadA = [&](int ch, int buf) {
        const int kb = kz * 512 + ch * 64;
        char* At = smem + buf * 16384;
#pragma unroll
        for (int t = 0; t < 4; ++t) {
            int idx = tid + t * 256;
            int r = idx >> 3, g = (idx & 7) * 8;
            const float* p = g_ADJ + (size_t)(m0 + r) * NN + kb + g;
            float4 f0 = *(const float4*)p;
            float4 f1 = *(const float4*)(p + 4);
            uint4 w;
            w.x = (f0.x > mean ? 0x3F80u : 0u) | ((f0.y > mean ? 0x3F80u : 0u) << 16);
            w.y = (f0.z > mean ? 0x3F80u : 0u) | ((f0.w > mean ? 0x3F80u : 0u) << 16);
            w.z = (f1.x > mean ? 0x3F80u : 0u) | ((f1.y > mean ? 0x3F80u : 0u) << 16);
            w.w = (f1.z > mean ? 0x3F80u : 0u) | ((f1.w > mean ? 0x3F80u : 0u) << 16);
            *(uint4*)(At + swz(r, g)) = w;
        }
    };

    float c[4][8][4] = {};
    issueB(0, 0);
    CP_COMMIT();
    int buf = 0;

    for (int ch = 0; ch < 8; ++ch) {
        CP_WAIT0();
        __syncthreads();
        if (ch < 7) { issueB(ch + 1, buf ^ 1); CP_COMMIT(); }
        loadA(ch, buf);
        __syncthreads();
        const uint32_t boA = buf * 16384, boB = buf * 32768;
#pragma unroll
        for (int s = 0; s < 4; ++s) {
            uint32_t a[4][4];
#pragma unroll
            for (int mt = 0; mt < 4; ++mt)
                ldsm4(a[mt], sb + oA + boA + swz(wm * 64 + mt * 16 + arow, s * 16 + akh));
#pragma unroll
            for (int np = 0; np < 4; ++np) {
                uint32_t bh[4], bl[4];
                ldsm4(bh, sb + oBh + boB + swz(wn * 64 + np * 16 + brow, s * 16 + bkh));
                ldsm4(bl, sb + oBl + boB + swz(wn * 64 + np * 16 + brow, s * 16 + bkh));
#pragma unroll
                for (int mt = 0; mt < 4; ++mt) {
#pragma unroll
                    for (int j = 0; j < 2; ++j) {
                        mma16816(c[mt][np * 2 + j], a[mt], bh[2 * j], bh[2 * j + 1]);
                        mma16816(c[mt][np * 2 + j], a[mt], bl[2 * j], bl[2 * j + 1]);
                    }
                }
            }
        }
        buf ^= 1;
    }

    float* Yp = g_Yp + (size_t)kz * ND;
    const int lr = lane >> 2, lc = (lane & 3) * 2;
#pragma unroll
    for (int mt = 0; mt < 4; ++mt)
#pragma unroll
        for (int nt = 0; nt < 8; ++nt) {
            int m = m0 + wm * 64 + mt * 16 + lr;
            int n = wn * 64 + nt * 8 + lc;
            *(float2*)&Yp[m * 256 + n] = make_float2(c[mt][nt][0], c[mt][nt][1]);
            *(float2*)&Yp[(m + 8) * 256 + n] = make_float2(c[mt][nt][2], c[mt][nt][3]);
        }
}

// Y = sum_k Yp[k] + X (deterministic fixed order; E=1 identity term)
__global__ void combine_Y(const float* __restrict__ X, float* __restrict__ Y)
{
    const float4* x4 = reinterpret_cast<const float4*>(X);
    const float4* p4 = reinterpret_cast<const float4*>(g_Yp);
    float4* y4 = reinterpret_cast<float4*>(Y);
    const int n4 = ND / 4;
    int stride = gridDim.x * blockDim.x;
    for (int i = blockIdx.x * blockDim.x + threadIdx.x; i < n4; i += stride) {
        float4 r = x4[i];
#pragma unroll
        for (int k = 0; k < KZ; ++k) {
            float4 a = p4[i + k * n4];
            r.x += a.x; r.y += a.y; r.z += a.z; r.w += a.w;
        }
        y4[i] = r;
    }
}

// ========== small GEMM via mma.sync: C[4096,256] = act(A @ W + b) ===========
// ABN: 0 = plain A, 1 = A := relu(A*bnscale[k]+bnshift[k])
// EPI: 0 ELU->f32  1 bias->f32  2 ELU->bf16 split  3 X=C,ACC=C  4 X=C,ACC+=C
//      5 G=(ACC+C)/3
#define SM_SMEM 81920
template <int ABN, int EPI>
__global__ __launch_bounds__(256, 1) void gemm_mma(
    const float* __restrict__ A, const __nv_bfloat16* __restrict__ Wth,
    const __nv_bfloat16* __restrict__ Wtl, const float* __restrict__ bias,
    float* __restrict__ C, __nv_bfloat16* __restrict__ Ch,
    __nv_bfloat16* __restrict__ Cl, float* __restrict__ ACC,
    float* __restrict__ G)
{
    extern __shared__ __align__(16) char smem[];
    const uint32_t sb = smem_u32(smem);
    const int tid = threadIdx.x, wid = tid >> 5, lane = tid & 31;
    const int n0 = blockIdx.x * 128, m0 = blockIdx.y * 64;
    const int wm = wid >> 2, wn = wid & 3;   // warp tile 32m x 32n

    const uint32_t oAh = 0, oAl = 8192, oBh = 16384, oBl = 49152;
    const int arow = lane & 15, akh = (lane >> 4) * 8;
    const int brow = ((lane >> 4) << 3) + (lane & 7), bkh = ((lane >> 3) & 1) * 8;

    auto issueB = [&](int ch, int buf) {
        const int kb = ch * 64;
        const uint32_t bo = buf * 16384;
#pragma unroll
        for (int t = 0; t < 4; ++t) {
            int idx = tid + t * 256;
            int r = idx >> 3, g = (idx & 7) * 8;
            uint32_t so = swz(r, g);
            cp16(sb + oBh + bo + so, Wth + (n0 + r) * 256 + kb + g);
            cp16(sb + oBl + bo + so, Wtl + (n0 + r) * 256 + kb + g);
        }
    };
    auto loadA = [&](int ch) {
        const int kb = ch * 64;
#pragma unroll
        for (int t = 0; t < 2; ++t) {
            int idx = tid + t * 256;
            int r = idx >> 3, g = (idx & 7) * 8;
            const float* p = A + (m0 + r) * 256 + kb + g;
            float v[8];
            *(float4*)&v[0] = *(const float4*)p;
            *(float4*)&v[4] = *(const float4*)(p + 4);
            if (ABN) {
                float4 s0 = *(const float4*)&g_bnscale[kb + g];
                float4 s1 = *(const float4*)&g_bnscale[kb + g + 4];
                float4 h0 = *(const float4*)&g_bnshift[kb + g];
                float4 h1 = *(const float4*)&g_bnshift[kb + g + 4];
                float sc[8] = {s0.x, s0.y, s0.z, s0.w, s1.x, s1.y, s1.z, s1.w};
                float sh[8] = {h0.x, h0.y, h0.z, h0.w, h1.x, h1.y, h1.z, h1.w};
#pragma unroll
                for (int j = 0; j < 8; ++j) v[j] = fmaxf(v[j] * sc[j] + sh[j], 0.0f);
            }
            uint4 wh, wl;
            float hi[8], lo[8];
#pragma unroll
            for (int j = 0; j < 8; ++j) {
                hi[j] = __bfloat162float(__float2bfloat16(v[j]));
                lo[j] = v[j] - hi[j];
            }
            wh = make_uint4(bf2pack(hi[0], hi[1]), bf2pack(hi[2], hi[3]),
                            bf2pack(hi[4], hi[5]), bf2pack(hi[6], hi[7]));
            wl = make_uint4(bf2pack(lo[0], lo[1]), bf2pack(lo[2], lo[3]),
                            bf2pack(lo[4], lo[5]), bf2pack(lo[6], lo[7]));
            *(uint4*)(smem + oAh + swz(r, g)) = wh;
            *(uint4*)(smem + oAl + swz(r, g)) = wl;
        }
    };

    float c[2][4][4] = {};
    issueB(0, 0);
    CP_COMMIT();
    int buf = 0;

    for (int ch = 0; ch < 4; ++ch) {
        CP_WAIT0();
        __syncthreads();
        if (ch < 3) { issueB(ch + 1, buf ^ 1); CP_COMMIT(); }
        loadA(ch);
        __syncthreads();
        const uint32_t boB = buf * 16384;
#pragma unroll
        for (int s = 0; s < 4; ++s) {
            uint32_t ah[2][4], al[2][4];
#pragma unroll
            for (int mt = 0; mt < 2; ++mt) {
                ldsm4(ah[mt], sb + oAh + swz(wm * 32 + mt * 16 + arow, s * 16 + akh));
                ldsm4(al[mt], sb + oAl + swz(wm * 32 + mt * 16 + arow, s * 16 + akh));
            }
#pragma unroll
            for (int np = 0; np < 2; ++np) {
                uint32_t bh[4], bl[4];
                ldsm4(bh, sb + oBh + boB + swz(wn * 32 + np * 16 + brow, s * 16 + bkh));
                ldsm4(bl, sb + oBl + boB + swz(wn * 32 + np * 16 + brow, s * 16 + bkh));
#pragma unroll
                for (int mt = 0; mt < 2; ++mt) {
#pragma unroll
                    for (int j = 0; j < 2; ++j) {
                        mma16816(c[mt][np * 2 + j], ah[mt], bh[2 * j], bh[2 * j + 1]);
                        mma16816(c[mt][np * 2 + j], ah[mt], bl[2 * j], bl[2 * j + 1]);
                        mma16816(c[mt][np * 2 + j], al[mt], bh[2 * j], bh[2 * j + 1]);
                    }
                }
            }
        }
        buf ^= 1;
    }

    const int lr = lane >> 2, lc = (lane & 3) * 2;
#pragma unroll
    for (int mt = 0; mt < 2; ++mt)
#pragma unroll
        for (int nt = 0; nt < 4; ++nt) {
            const int n = n0 + wn * 32 + nt * 8 + lc;
            float2 bv = *(const float2*)&bias[n];
#pragma unroll
            for (int h = 0; h < 2; ++h) {
                const int m = m0 + wm * 32 + mt * 16 + lr + h * 8;
                float v0 = c[mt][nt][h * 2 + 0] + bv.x;
                float v1 = c[mt][nt][h * 2 + 1] + bv.y;
                if (EPI == 0 || EPI == 2) { v0 = eluf(v0); v1 = eluf(v1); }
                if (EPI == 2) {
                    float h0 = __bfloat162float(__float2bfloat16(v0));
                    float h1 = __bfloat162float(__float2bfloat16(v1));
                    *(uint32_t*)&Ch[m * 256 + n] = bf2pack(h0, h1);
                    *(uint32_t*)&Cl[m * 256 + n] = bf2pack(v0 - h0, v1 - h1);
                } else if (EPI == 5) {
                    float2 ac = *(const float2*)&ACC[m * 256 + n];
                    *(float2*)&G[m * 256 + n] =
                        make_float2((ac.x + v0) * (1.0f / 3.0f),
                                    (ac.y + v1) * (1.0f / 3.0f));
                } else {
                    *(float2*)&C[m * 256 + n] = make_float2(v0, v1);
                    if (EPI == 3)
                        *(float2*)&ACC[m * 256 + n] = make_float2(v0, v1);
                    if (EPI == 4) {
                        float2 ac = *(const float2*)&ACC[m * 256 + n];
                        *(float2*)&ACC[m * 256 + n] = make_float2(ac.x + v0, ac.y + v1);
                    }
                }
            }
        }
}

// =============== weight transpose + bf16 split (8 mats per branch) =========
__global__ void wt_split(const float* __restrict__ adjW,
                         const float* __restrict__ mlpW)
{
    const int mat = blockIdx.z;
    const float* src = (mat < 2) ? adjW + mat * 65536 : mlpW + (mat - 2) * 65536;
    __shared__ float t[32][33];
    const int r0 = blockIdx.x * 32, c0 = blockIdx.y * 32;  // r = k, c = n
    const int x = threadIdx.x, y = threadIdx.y;
    for (int i = 0; i < 32; i += 8)
        t[y + i][x] = src[(r0 + y + i) * 256 + c0 + x];
    __syncthreads();
    for (int i = 0; i < 32; i += 8) {
        float v = t[x][y + i];  // W[k=r0+x][n=c0+y+i]
        __nv_bfloat16 h = __float2bfloat16(v);
        float hf = __bfloat162float(h);
        g_Wth[mat * 65536 + (c0 + y + i) * 256 + r0 + x] = h;
        g_Wtl[mat * 65536 + (c0 + y + i) * 256 + r0 + x] = __float2bfloat16(v - hf);
    }
}

// =============== X transpose + bf16 split: [4096,256] -> [256,4096] ========
__global__ void xt_split(const float* __restrict__ X)
{
    __shared__ float t[32][33];
    const int r0 = blockIdx.x * 32, c0 = blockIdx.y * 32;
    const int x = threadIdx.x, y = threadIdx.y;
    for (int i = 0; i < 32; i += 8)
        t[y + i][x] = X[(r0 + y + i) * 256 + c0 + x];
    __syncthreads();
    for (int i = 0; i < 32; i += 8) {
        float v = t[x][y + i];
        __nv_bfloat16 h = __float2bfloat16(v);
        float hf = __bfloat162float(h);
        g_Xth[(c0 + y + i) * 4096 + r0 + x] = h;
        g_Xtl[(c0 + y + i) * 4096 + r0 + x] = __float2bfloat16(v - hf);
    }
}

// ---------------- BatchNorm stats (deterministic 2-stage) -------------------
__global__ void colstats(const float* __restrict__ H)
{
    int t = threadIdx.x;
    int r0 = blockIdx.x * 128;
    float s = 0.0f, q = 0.0f;
    for (int r = r0; r < r0 + 128; ++r) {
        float v = H[r * 256 + t];
        s += v;
        q += v * v;
    }
    g_colpart[blockIdx.x * 512 + t] = s;
    g_colpart[blockIdx.x * 512 + 256 + t] = q;
}

__global__ void finalize_stats(const float* __restrict__ gamma,
                               const float* __restrict__ beta)
{
    int t = threadIdx.x;
    float s = 0.0f, q = 0.0f;
    for (int b = 0; b < 32; ++b) {
        s += g_colpart[b * 512 + t];
        q += g_colpart[b * 512 + 256 + t];
    }
    float mu = s * (1.0f / (float)NN);
    float var = q * (1.0f / (float)NN) - mu * mu;
    float rstd = rsqrtf(var + 1e-5f);
    float sc = gamma[t] * rstd;
    g_bnscale[t] = sc;
    g_bnshift[t] = beta[t] - mu * sc;
}

// ---------------- MSE ---------------------------------------------------------
__global__ void mse_partial()
{
    int t = threadIdx.x, b = blockIdx.x;
    float s0 = 0.0f, s1 = 0.0f, s2 = 0.0f;
    for (int i = b * 256 + t; i < ND; i += 256 * 256) {
        float ga = g_G[3][i];
        float d0 = g_G[0][i] - ga;
        float d1 = g_G[1][i] - ga;
        float d2 = g_G[2][i] - ga;
        s0 += d0 * d0;
        s1 += d1 * d1;
        s2 += d2 * d2;
    }
    __shared__ float r[3][256];
    r[0][t] = s0; r[1][t] = s1; r[2][t] = s2;
    __syncthreads();
    for (int o = 128; o > 0; o >>= 1) {
        if (t < o) {
            r[0][t] += r[0][t + o];
            r[1][t] += r[1][t + o];
            r[2][t] += r[2][t + o];
        }
        __syncthreads();
    }
    if (t == 0) {
        g_msepart[b * 3 + 0] = r[0][0];
        g_msepart[b * 3 + 1] = r[1][0];
        g_msepart[b * 3 + 2] = r[2][0];
    }
}

__global__ void mse_final(float* __restrict__ out)
{
    int t = threadIdx.x;
    __shared__ float r[256];
    for (int v = 0; v < 3; ++v) {
        r[t] = g_msepart[t * 3 + v];
        __syncthreads();
        for (int o = 128; o > 0; o >>= 1) {
            if (t < o) r[t] += r[t + o];
            __syncthreads();
        }
        if (t == 0) out[v] = r[0] * (1.0f / (float)ND);
        __syncthreads();
    }
}

// ---------------- host driver ------------------------------------------------
struct Scratch {
    float *X, *H1, *Y, *Hm, *ACC, *G;
    __nv_bfloat16 *Hh, *Hl, *Wth, *Wtl;
};

static void run_gin(const Scratch& p, const float* Xin,
                    const float* adjW, const float* ab,
                    const float* mW, const float* mb, const float* mbn,
                    int branch)
{
    const dim3 g_sm(2, 64);
    wt_split<<<dim3(8, 8, 8), dim3(32, 8)>>>(adjW, mW);
    for (int l = 0; l < LL; ++l) {
        const float* A0 = (l == 0) ? Xin : p.X;
        // adjacency learner
        gemm_mma<0, 0><<<g_sm, 256, SM_SMEM>>>(
            A0, p.Wth, p.Wtl, ab, p.H1, nullptr, nullptr, nullptr, nullptr);
        gemm_mma<0, 2><<<g_sm, 256, SM_SMEM>>>(
            p.H1, p.Wth + 65536, p.Wtl + 65536, ab + 256,
            nullptr, p.Hh, p.Hl, nullptr, nullptr);
        adj_mma<<<NTB, 256, ADJ_SMEM>>>(p.Hh, p.Hl);
        reduce_adjsum<<<1, 512>>>();
        // aggregate (oh + I) @ X
        xt_split<<<dim3(128, 8), dim3(32, 8)>>>(A0);
        thresh_mma<<<dim3(32, KZ), 256, THR_SMEM>>>();
        combine_Y<<<512, 256>>>(A0, p.Y);
        // GIN MLP
        const __nv_bfloat16* W0h = p.Wth + (2 + 2 * l) * 65536;
        const __nv_bfloat16* W0l = p.Wtl + (2 + 2 * l) * 65536;
        const __nv_bfloat16* W1h = p.Wth + (3 + 2 * l) * 65536;
        const __nv_bfloat16* W1l = p.Wtl + (3 + 2 * l) * 65536;
        const float* b0 = mb + l * 512;
        const float* b1 = b0 + 256;
        const float* gamma = mbn + l * 512;
        const float* beta = gamma + 256;
        gemm_mma<0, 1><<<g_sm, 256, SM_SMEM>>>(
            p.Y, W0h, W0l, b0, p.Hm, nullptr, nullptr, nullptr, nullptr);
        colstats<<<32, 256>>>(p.Hm);
        finalize_stats<<<1, 256>>>(gamma, beta);
        if (l == 0)
            gemm_mma<1, 3><<<g_sm, 256, SM_SMEM>>>(
                p.Hm, W1h, W1l, b1, p.X, nullptr, nullptr, p.ACC, nullptr);
        else if (l == 1)
            gemm_mma<1, 4><<<g_sm, 256, SM_SMEM>>>(
                p.Hm, W1h, W1l, b1, p.X, nullptr, nullptr, p.ACC, nullptr);
        else
            gemm_mma<1, 5><<<g_sm, 256, SM_SMEM>>>(
                p.Hm, W1h, W1l, b1, nullptr, nullptr, nullptr, p.ACC,
                p.G + (size_t)branch * ND);
    }
}

extern "C" void kernel_launch(void* const* d_in, const int* in_sizes, int n_in,
                              void* d_out, int out_size)
{
    const float* QV = (const float*)d_in[0];
    const float* Q  = (const float*)d_in[1];
    const float* V  = (const float*)d_in[2];
    const float* A  = (const float*)d_in[3];
    const float* adjW_qv  = (const float*)d_in[4];
    const float* adjb_qv  = (const float*)d_in[5];
    const float* mlpW_qv  = (const float*)d_in[6];
    const float* mlpb_qv  = (const float*)d_in[7];
    const float* mlpbn_qv = (const float*)d_in[8];
    const float* adjW_t   = (const float*)d_in[9];
    const float* adjb_t   = (const float*)d_in[10];
    const float* mlpW_t   = (const float*)d_in[11];
    const float* mlpb_t   = (const float*)d_in[12];
    const float* mlpbn_t  = (const float*)d_in[13];
    const float* adjW_v   = (const float*)d_in[14];
    const float* adjb_v   = (const float*)d_in[15];
    const float* mlpW_v   = (const float*)d_in[16];
    const float* mlpb_v   = (const float*)d_in[17];
    const float* mlpbn_v  = (const float*)d_in[18];

    cudaFuncSetAttribute(adj_mma, cudaFuncAttributeMaxDynamicSharedMemorySize,
                         ADJ_SMEM);
    cudaFuncSetAttribute(thresh_mma, cudaFuncAttributeMaxDynamicSharedMemorySize,
                         THR_SMEM);
    cudaFuncSetAttribute(gemm_mma<0, 0>, cudaFuncAttributeMaxDynamicSharedMemorySize, SM_SMEM);
    cudaFuncSetAttribute(gemm_mma<0, 1>, cudaFuncAttributeMaxDynamicSharedMemorySize, SM_SMEM);
    cudaFuncSetAttribute(gemm_mma<0, 2>, cudaFuncAttributeMaxDynamicSharedMemorySize, SM_SMEM);
    cudaFuncSetAttribute(gemm_mma<1, 3>, cudaFuncAttributeMaxDynamicSharedMemorySize, SM_SMEM);
    cudaFuncSetAttribute(gemm_mma<1, 4>, cudaFuncAttributeMaxDynamicSharedMemorySize, SM_SMEM);
    cudaFuncSetAttribute(gemm_mma<1, 5>, cudaFuncAttributeMaxDynamicSharedMemorySize, SM_SMEM);

    Scratch p;
    cudaGetSymbolAddress((void**)&p.X, g_X);
    cudaGetSymbolAddress((void**)&p.H1, g_H1);
    cudaGetSymbolAddress((void**)&p.Y, g_Y);
    cudaGetSymbolAddress((void**)&p.Hm, g_Hm);
    cudaGetSymbolAddress((void**)&p.ACC, g_ACC);
    cudaGetSymbolAddress((void**)&p.G, g_G);
    cudaGetSymbolAddress((void**)&p.Hh, g_Hh);
    cudaGetSymbolAddress((void**)&p.Hl, g_Hl);
    cudaGetSymbolAddress((void**)&p.Wth, g_Wth);
    cudaGetSymbolAddress((void**)&p.Wtl, g_Wtl);

    run_gin(p, QV, adjW_qv, adjb_qv, mlpW_qv, mlpb_qv, mlpbn_qv, 0);
    run_gin(p, Q,  adjW_t,  adjb_t,  mlpW_t,  mlpb_t,  mlpbn_t,  1);
    run_gin(p, V,  adjW_v,  adjb_v,  mlpW_v,  mlpb_v,  mlpbn_v,  2);
    run_gin(p, A,  adjW_t,  adjb_t,  mlpW_t,  mlpb_t,  mlpbn_t,  3);

    mse_partial<<<256, 256>>>();
    mse_final<<<1, 256>>>((float*)d_out);
}

// round 6
// speedup vs baseline: 6.7527x; 1.2126x over previous
#include <cuda_runtime.h>
#include <cuda_bf16.h>
#include <math.h>
#include <stdint.h>

#define NN 4096
#define DD 256
#define LL 3
#define ND (NN * DD)
#define NTB 528   // 32*33/2 upper-triangular 128x128 tiles
#define KZ 2      // split-K slabs for thresh

// ---------------- scratch (device globals; no allocation allowed) ----------
__device__ float g_X[4][ND];
__device__ float g_H1[4][ND];
__device__ float g_Y[4][ND];
__device__ float g_Hm[4][ND];
__device__ float g_ACC[4][ND];
__device__ float g_G[4][ND];
__device__ __nv_bfloat16 g_P[4][NN * NN];     // thresholded adj {0,1}, 128 MB
__device__ float g_Yp[KZ][4][ND];
__device__ __nv_bfloat16 g_Hh[4][ND];
__device__ __nv_bfloat16 g_Hl[4][ND];
__device__ __nv_bfloat16 g_Xth[4][ND];        // X^T bf16 hi [256,4096]
__device__ __nv_bfloat16 g_Xtl[4][ND];
__device__ __nv_bfloat16 g_Wth[3][8][DD * DD];
__device__ __nv_bfloat16 g_Wtl[3][8][DD * DD];
__device__ float g_sumpart[4][32][DD];
__device__ float g_mean[4];
__device__ float g_colpart[4][32 * 512];
__device__ float g_bnscale[4][DD];
__device__ float g_bnshift[4][DD];
__device__ float g_msepart[256 * 3];

__device__ __forceinline__ float eluf(float x) {
    return x > 0.0f ? x : (expf(x) - 1.0f);
}
__device__ __forceinline__ int wset_of(int br) {
    return (br == 0) ? 0 : (br == 2 ? 2 : 1);
}

// =================== warp MMA / async helpers ================================
__device__ __forceinline__ uint32_t smem_u32(const void* p) {
    uint32_t a;
    asm("{ .reg .u64 t; cvta.to.shared.u64 t, %1; cvt.u32.u64 %0, t; }"
        : "=r"(a) : "l"(p));
    return a;
}
__device__ __forceinline__ void ldsm4(uint32_t (&r)[4], uint32_t addr) {
    asm volatile("ldmatrix.sync.aligned.m8n8.x4.shared.b16 {%0,%1,%2,%3}, [%4];"
                 : "=r"(r[0]), "=r"(r[1]), "=r"(r[2]), "=r"(r[3]) : "r"(addr));
}
__device__ __forceinline__ void mma16816(float (&d)[4], const uint32_t (&a)[4],
                                         uint32_t b0, uint32_t b1) {
    asm volatile(
        "mma.sync.aligned.m16n8k16.row.col.f32.bf16.bf16.f32 "
        "{%0,%1,%2,%3}, {%4,%5,%6,%7}, {%8,%9}, {%0,%1,%2,%3};"
        : "+f"(d[0]), "+f"(d[1]), "+f"(d[2]), "+f"(d[3])
        : "r"(a[0]), "r"(a[1]), "r"(a[2]), "r"(a[3]), "r"(b0), "r"(b1));
}
__device__ __forceinline__ void cp16(uint32_t dst, const void* src) {
    asm volatile("cp.async.ca.shared.global [%0], [%1], 16;" :: "r"(dst), "l"(src));
}
#define CP_COMMIT() asm volatile("cp.async.commit_group;" ::: "memory")
#define CP_WAIT0()  asm volatile("cp.async.wait_group 0;" ::: "memory")

__device__ __forceinline__ uint32_t swz(uint32_t row, uint32_t k) {
    uint32_t o = row * 128u + k * 2u;
    return o ^ ((o >> 3) & 0x70u);
}
__device__ __forceinline__ uint32_t bf2pack(float a, float b) {
    __nv_bfloat162 t = __floats2bfloat162_rn(a, b);
    return *reinterpret_cast<uint32_t*>(&t);
}

// =========== mean of H@H^T via column-sum identity: ||colsum||^2/N^2 ========
__global__ void colsum_part()
{
    const int br = blockIdx.y, blk = blockIdx.x, t = threadIdx.x;
    float s = 0.0f;
    for (int r = blk * 128; r < blk * 128 + 128; ++r)
        s += __bfloat162float(g_Hh[br][r * 256 + t]) +
             __bfloat162float(g_Hl[br][r * 256 + t]);
    g_sumpart[br][blk][t] = s;
}

__global__ void colsum_mean()
{
    const int br = blockIdx.x, t = threadIdx.x;
    float s = 0.0f;
    for (int b = 0; b < 32; ++b) s += g_sumpart[br][b][t];
    __shared__ float red[256];
    red[t] = s * s;
    __syncthreads();
    for (int o = 128; o > 0; o >>= 1) {
        if (t < o) red[t] += red[t + o];
        __syncthreads();
    }
    if (t == 0) g_mean[br] = red[0] * (1.0f / ((float)NN * (float)NN));
}

// ====== P = (H@H^T > mean) as bf16 {0,1}; symmetric tiles + mirror ==========
#define ADJ_SMEM 131072
__global__ __launch_bounds__(256, 1) void adj_mma()
{
    extern __shared__ __align__(16) char smem[];
    const uint32_t sb = smem_u32(smem);
    const int tid = threadIdx.x, wid = tid >> 5, lane = tid & 31;
    const int br = blockIdx.y;
    const __nv_bfloat16* Hh = g_Hh[br];
    const __nv_bfloat16* Hl = g_Hl[br];
    __nv_bfloat16* P = g_P[br];

    int b = blockIdx.x, bi = 0, rem = b;
    while (rem >= 32 - bi) { rem -= 32 - bi; ++bi; }
    const int bj = bi + rem;
    const bool diag = (bi == bj);
    const int m0 = bi * 128, n0 = bj * 128;
    const int wm = wid >> 2, wn = wid & 3;   // 2x4 warp grid, warp tile 64x32

    const uint32_t oAh = 0, oAl = 32768;
    const uint32_t oBh = diag ? 0u : 65536u, oBl = diag ? 32768u : 98304u;
    const int arow = lane & 15, akh = (lane >> 4) * 8;
    const int brow = ((lane >> 4) << 3) + (lane & 7), bkh = ((lane >> 3) & 1) * 8;

    auto issue = [&](int ch, int buf) {
        const int kb = ch * 64;
        const uint32_t bo = buf * 16384;
#pragma unroll
        for (int t = 0; t < 4; ++t) {
            int idx = tid + t * 256;
            int r = idx >> 3, g = (idx & 7) * 8;
            uint32_t so = swz(r, g);
            cp16(sb + oAh + bo + so, Hh + (m0 + r) * 256 + kb + g);
            cp16(sb + oAl + bo + so, Hl + (m0 + r) * 256 + kb + g);
            if (!diag) {
                cp16(sb + oBh + bo + so, Hh + (n0 + r) * 256 + kb + g);
                cp16(sb + oBl + bo + so, Hl + (n0 + r) * 256 + kb + g);
            }
        }
    };

    float c[4][4][4] = {};
    issue(0, 0);
    CP_COMMIT();
    int buf = 0;

    for (int ch = 0; ch < 4; ++ch) {
        CP_WAIT0();
        __syncthreads();
        if (ch < 3) { issue(ch + 1, buf ^ 1); CP_COMMIT(); }
        const uint32_t bo = buf * 16384;
#pragma unroll
        for (int s = 0; s < 4; ++s) {
            uint32_t ah[4][4], al[4][4];
#pragma unroll
            for (int mt = 0; mt < 4; ++mt) {
                ldsm4(ah[mt], sb + oAh + bo + swz(wm * 64 + mt * 16 + arow, s * 16 + akh));
                ldsm4(al[mt], sb + oAl + bo + swz(wm * 64 + mt * 16 + arow, s * 16 + akh));
            }
#pragma unroll
            for (int np = 0; np < 2; ++np) {
                uint32_t bh[4], bl[4];
                ldsm4(bh, sb + oBh + bo + swz(wn * 32 + np * 16 + brow, s * 16 + bkh));
                ldsm4(bl, sb + oBl + bo + swz(wn * 32 + np * 16 + brow, s * 16 + bkh));
#pragma unroll
                for (int mt = 0; mt < 4; ++mt) {
#pragma unroll
                    for (int j = 0; j < 2; ++j) {
                        mma16816(c[mt][np * 2 + j], ah[mt], bh[2 * j], bh[2 * j + 1]);
                        mma16816(c[mt][np * 2 + j], ah[mt], bl[2 * j], bl[2 * j + 1]);
                        mma16816(c[mt][np * 2 + j], al[mt], bh[2 * j], bh[2 * j + 1]);
                    }
                }
            }
        }
        buf ^= 1;
    }

    // threshold in registers; write upper tile
    const float mean = g_mean[br];
    const int lr = lane >> 2, lc = (lane & 3) * 2;
    float p[4][4][4];
#pragma unroll
    for (int mt = 0; mt < 4; ++mt)
#pragma unroll
        for (int nt = 0; nt < 4; ++nt) {
#pragma unroll
            for (int q = 0; q < 4; ++q)
                p[mt][nt][q] = (c[mt][nt][q] > mean) ? 1.0f : 0.0f;
            int m = m0 + wm * 64 + mt * 16 + lr;
            int n = n0 + wn * 32 + nt * 8 + lc;
            *(uint32_t*)&P[m * NN + n] = bf2pack(p[mt][nt][0], p[mt][nt][1]);
            *(uint32_t*)&P[(m + 8) * NN + n] = bf2pack(p[mt][nt][2], p[mt][nt][3]);
        }

    // mirror via bf16 smem transpose
    if (!diag) {
        __nv_bfloat16* T = reinterpret_cast<__nv_bfloat16*>(smem);  // [128][136]
        __syncthreads();
#pragma unroll
        for (int mt = 0; mt < 4; ++mt)
#pragma unroll
            for (int nt = 0; nt < 4; ++nt) {
                int ml = wm * 64 + mt * 16 + lr;
                int nl = wn * 32 + nt * 8 + lc;
                T[nl * 136 + ml] = __float2bfloat16(p[mt][nt][0]);
                T[(nl + 1) * 136 + ml] = __float2bfloat16(p[mt][nt][1]);
                T[nl * 136 + ml + 8] = __float2bfloat16(p[mt][nt][2]);
                T[(nl + 1) * 136 + ml + 8] = __float2bfloat16(p[mt][nt][3]);
            }
        __syncthreads();
        int n = tid >> 1, mh = (tid & 1) * 64;
        uint4* dst = reinterpret_cast<uint4*>(&P[(n0 + n) * NN + m0 + mh]);
        const uint4* src = reinterpret_cast<const uint4*>(T + n * 136 + mh);
#pragma unroll
        for (int q = 0; q < 8; ++q) dst[q] = src[q];
    }
}

// ====== Yp[kz] = P[:, slab] @ X[slab]: cp.async A (bf16 P) and B ============
#define THR_SMEM 163840
__global__ __launch_bounds__(256, 1) void thresh_mma()
{
    extern __shared__ __align__(16) char smem[];
    const uint32_t sb = smem_u32(smem);
    const int tid = threadIdx.x, wid = tid >> 5, lane = tid & 31;
    const int m0 = blockIdx.x * 128;
    const int kz = blockIdx.y;
    const int br = blockIdx.z;
    const __nv_bfloat16* P = g_P[br];
    const __nv_bfloat16* Xth = g_Xth[br];
    const __nv_bfloat16* Xtl = g_Xtl[br];
    const int wm = wid >> 2, wn = wid & 3;   // warp tile 64m x 64n

    const uint32_t oA = 0, oBh = 32768, oBl = 98304;
    const int arow = lane & 15, akh = (lane >> 4) * 8;
    const int brow = ((lane >> 4) << 3) + (lane & 7), bkh = ((lane >> 3) & 1) * 8;

    auto issue = [&](int ch, int buf) {
        const int kb = kz * (NN / KZ) + ch * 64;
#pragma unroll
        for (int t = 0; t < 4; ++t) {
            int idx = tid + t * 256;
            int r = idx >> 3, g = (idx & 7) * 8;
            cp16(sb + oA + buf * 16384 + swz(r, g),
                 P + (size_t)(m0 + r) * NN + kb + g);
        }
#pragma unroll
        for (int t = 0; t < 8; ++t) {
            int idx = tid + t * 256;
            int r = idx >> 3, g = (idx & 7) * 8;
            uint32_t so = swz(r, g);
            cp16(sb + oBh + buf * 32768 + so, Xth + r * 4096 + kb + g);
            cp16(sb + oBl + buf * 32768 + so, Xtl + r * 4096 + kb + g);
        }
    };

    float c[4][8][4] = {};
    issue(0, 0);
    CP_COMMIT();
    int buf = 0;
    const int NCH = (NN / KZ) / 64;

    for (int ch = 0; ch < NCH; ++ch) {
        CP_WAIT0();
        __syncthreads();
        if (ch < NCH - 1) { issue(ch + 1, buf ^ 1); CP_COMMIT(); }
        const uint32_t boA = buf * 16384, boB = buf * 32768;
#pragma unroll
        for (int s = 0; s < 4; ++s) {
            uint32_t a[4][4];
#pragma unroll
            for (int mt = 0; mt < 4; ++mt)
                ldsm4(a[mt], sb + oA + boA + swz(wm * 64 + mt * 16 + arow, s * 16 + akh));
#pragma unroll
            for (int np = 0; np < 4; ++np) {
                uint32_t bh[4], bl[4];
                ldsm4(bh, sb + oBh + boB + swz(wn * 64 + np * 16 + brow, s * 16 + bkh));
                ldsm4(bl, sb + oBl + boB + swz(wn * 64 + np * 16 + brow, s * 16 + bkh));
#pragma unroll
                for (int mt = 0; mt < 4; ++mt) {
#pragma unroll
                    for (int j = 0; j < 2; ++j) {
                        mma16816(c[mt][np * 2 + j], a[mt], bh[2 * j], bh[2 * j + 1]);
                        mma16816(c[mt][np * 2 + j], a[mt], bl[2 * j], bl[2 * j + 1]);
                    }
                }
            }
        }
        buf ^= 1;
    }

    float* Yp = g_Yp[kz][br];
    const int lr = lane >> 2, lc = (lane & 3) * 2;
#pragma unroll
    for (int mt = 0; mt < 4; ++mt)
#pragma unroll
        for (int nt = 0; nt < 8; ++nt) {
            int m = m0 + wm * 64 + mt * 16 + lr;
            int n = wn * 64 + nt * 8 + lc;
            *(float2*)&Yp[m * 256 + n] = make_float2(c[mt][nt][0], c[mt][nt][1]);
            *(float2*)&Yp[(m + 8) * 256 + n] = make_float2(c[mt][nt][2], c[mt][nt][3]);
        }
}

// Y = Yp[0] + Yp[1] + X
__global__ void combine_Y(const float* __restrict__ x0, const float* __restrict__ x1,
                          const float* __restrict__ x2, const float* __restrict__ x3)
{
    const int br = blockIdx.y;
    const float* Xs[4] = {x0, x1, x2, x3};
    const float4* x4 = reinterpret_cast<const float4*>(Xs[br]);
    const float4* p0 = reinterpret_cast<const float4*>(g_Yp[0][br]);
    const float4* p1 = reinterpret_cast<const float4*>(g_Yp[1][br]);
    float4* y4 = reinterpret_cast<float4*>(g_Y[br]);
    const int n4 = ND / 4;
    int stride = gridDim.x * blockDim.x;
    for (int i = blockIdx.x * blockDim.x + threadIdx.x; i < n4; i += stride) {
        float4 x = x4[i], a = p0[i], b = p1[i];
        y4[i] = make_float4(x.x + (a.x + b.x), x.y + (a.y + b.y),
                            x.z + (a.z + b.z), x.w + (a.w + b.w));
    }
}

// ========== small GEMM via mma.sync, batched over 4 branches ================
#define SM_SMEM 81920
template <int ABN, int EPI>
__global__ __launch_bounds__(256, 1) void gemm_mma(
    const float* __restrict__ a0, const float* __restrict__ a1,
    const float* __restrict__ a2, const float* __restrict__ a3, int mat,
    const float* __restrict__ b0, const float* __restrict__ b1,
    const float* __restrict__ b2, const float* __restrict__ b3)
{
    extern __shared__ __align__(16) char smem[];
    const uint32_t sb = smem_u32(smem);
    const int tid = threadIdx.x, wid = tid >> 5, lane = tid & 31;
    const int n0 = blockIdx.x * 128, m0 = blockIdx.y * 64;
    const int br = blockIdx.z;
    const float* As4[4] = {a0, a1, a2, a3};
    const float* Bs4[4] = {b0, b1, b2, b3};
    const float* A = As4[br];
    const float* bias = Bs4[br];
    const int ws = wset_of(br);
    const __nv_bfloat16* Wth = g_Wth[ws][mat];
    const __nv_bfloat16* Wtl = g_Wtl[ws][mat];
    const int wm = wid >> 2, wn = wid & 3;   // warp tile 32m x 32n

    const uint32_t oAh = 0, oAl = 8192, oBh = 16384, oBl = 49152;
    const int arow = lane & 15, akh = (lane >> 4) * 8;
    const int brow = ((lane >> 4) << 3) + (lane & 7), bkh = ((lane >> 3) & 1) * 8;

    auto issueB = [&](int ch, int buf) {
        const int kb = ch * 64;
        const uint32_t bo = buf * 16384;
#pragma unroll
        for (int t = 0; t < 4; ++t) {
            int idx = tid + t * 256;
            int r = idx >> 3, g = (idx & 7) * 8;
            uint32_t so = swz(r, g);
            cp16(sb + oBh + bo + so, Wth + (n0 + r) * 256 + kb + g);
            cp16(sb + oBl + bo + so, Wtl + (n0 + r) * 256 + kb + g);
        }
    };
    auto loadA = [&](int ch) {
        const int kb = ch * 64;
#pragma unroll
        for (int t = 0; t < 2; ++t) {
            int idx = tid + t * 256;
            int r = idx >> 3, g = (idx & 7) * 8;
            const float* p = A + (m0 + r) * 256 + kb + g;
            float v[8];
            *(float4*)&v[0] = *(const float4*)p;
            *(float4*)&v[4] = *(const float4*)(p + 4);
            if (ABN) {
                float4 s0 = *(const float4*)&g_bnscale[br][kb + g];
                float4 s1 = *(const float4*)&g_bnscale[br][kb + g + 4];
                float4 h0 = *(const float4*)&g_bnshift[br][kb + g];
                float4 h1 = *(const float4*)&g_bnshift[br][kb + g + 4];
                float sc[8] = {s0.x, s0.y, s0.z, s0.w, s1.x, s1.y, s1.z, s1.w};
                float sh[8] = {h0.x, h0.y, h0.z, h0.w, h1.x, h1.y, h1.z, h1.w};
#pragma unroll
                for (int j = 0; j < 8; ++j) v[j] = fmaxf(v[j] * sc[j] + sh[j], 0.0f);
            }
            float hi[8], lo[8];
#pragma unroll
            for (int j = 0; j < 8; ++j) {
                hi[j] = __bfloat162float(__float2bfloat16(v[j]));
                lo[j] = v[j] - hi[j];
            }
            *(uint4*)(smem + oAh + swz(r, g)) =
                make_uint4(bf2pack(hi[0], hi[1]), bf2pack(hi[2], hi[3]),
                           bf2pack(hi[4], hi[5]), bf2pack(hi[6], hi[7]));
            *(uint4*)(smem + oAl + swz(r, g)) =
                make_uint4(bf2pack(lo[0], lo[1]), bf2pack(lo[2], lo[3]),
                           bf2pack(lo[4], lo[5]), bf2pack(lo[6], lo[7]));
        }
    };

    float c[2][4][4] = {};
    issueB(0, 0);
    CP_COMMIT();
    int buf = 0;

    for (int ch = 0; ch < 4; ++ch) {
        CP_WAIT0();
        __syncthreads();
        if (ch < 3) { issueB(ch + 1, buf ^ 1); CP_COMMIT(); }
        loadA(ch);
        __syncthreads();
        const uint32_t boB = buf * 16384;
#pragma unroll
        for (int s = 0; s < 4; ++s) {
            uint32_t ah[2][4], al[2][4];
#pragma unroll
            for (int mt = 0; mt < 2; ++mt) {
                ldsm4(ah[mt], sb + oAh + swz(wm * 32 + mt * 16 + arow, s * 16 + akh));
                ldsm4(al[mt], sb + oAl + swz(wm * 32 + mt * 16 + arow, s * 16 + akh));
            }
#pragma unroll
            for (int np = 0; np < 2; ++np) {
                uint32_t bh[4], bl[4];
                ldsm4(bh, sb + oBh + boB + swz(wn * 32 + np * 16 + brow, s * 16 + bkh));
                ldsm4(bl, sb + oBl + boB + swz(wn * 32 + np * 16 + brow, s * 16 + bkh));
#pragma unroll
                for (int mt = 0; mt < 2; ++mt) {
#pragma unroll
                    for (int j = 0; j < 2; ++j) {
                        mma16816(c[mt][np * 2 + j], ah[mt], bh[2 * j], bh[2 * j + 1]);
                        mma16816(c[mt][np * 2 + j], ah[mt], bl[2 * j], bl[2 * j + 1]);
                        mma16816(c[mt][np * 2 + j], al[mt], bh[2 * j], bh[2 * j + 1]);
                    }
                }
            }
        }
        buf ^= 1;
    }

    const int lr = lane >> 2, lc = (lane & 3) * 2;
#pragma unroll
    for (int mt = 0; mt < 2; ++mt)
#pragma unroll
        for (int nt = 0; nt < 4; ++nt) {
            const int n = n0 + wn * 32 + nt * 8 + lc;
            float2 bv = *(const float2*)&bias[n];
#pragma unroll
            for (int h = 0; h < 2; ++h) {
                const int m = m0 + wm * 32 + mt * 16 + lr + h * 8;
                float v0 = c[mt][nt][h * 2 + 0] + bv.x;
                float v1 = c[mt][nt][h * 2 + 1] + bv.y;
                if (EPI == 0 || EPI == 2) { v0 = eluf(v0); v1 = eluf(v1); }
                if (EPI == 0) {
                    *(float2*)&g_H1[br][m * 256 + n] = make_float2(v0, v1);
                } else if (EPI == 1) {
                    *(float2*)&g_Hm[br][m * 256 + n] = make_float2(v0, v1);
                } else if (EPI == 2) {
                    float h0 = __bfloat162float(__float2bfloat16(v0));
                    float h1 = __bfloat162float(__float2bfloat16(v1));
                    *(uint32_t*)&g_Hh[br][m * 256 + n] = bf2pack(h0, h1);
                    *(uint32_t*)&g_Hl[br][m * 256 + n] = bf2pack(v0 - h0, v1 - h1);
                } else if (EPI == 5) {
                    float2 ac = *(const float2*)&g_ACC[br][m * 256 + n];
                    *(float2*)&g_G[br][m * 256 + n] =
                        make_float2((ac.x + v0) * (1.0f / 3.0f),
                                    (ac.y + v1) * (1.0f / 3.0f));
                } else {
                    *(float2*)&g_X[br][m * 256 + n] = make_float2(v0, v1);
                    if (EPI == 3)
                        *(float2*)&g_ACC[br][m * 256 + n] = make_float2(v0, v1);
                    if (EPI == 4) {
                        float2 ac = *(const float2*)&g_ACC[br][m * 256 + n];
                        *(float2*)&g_ACC[br][m * 256 + n] =
                            make_float2(ac.x + v0, ac.y + v1);
                    }
                }
            }
        }
}

// =============== weight transpose + bf16 split (3 sets x 8 mats) ============
__global__ void wt_split(const float* __restrict__ aw0, const float* __restrict__ aw1,
                         const float* __restrict__ aw2, const float* __restrict__ mw0,
                         const float* __restrict__ mw1, const float* __restrict__ mw2)
{
    const int z = blockIdx.z, ws = z >> 3, mat = z & 7;
    const float* aws[3] = {aw0, aw1, aw2};
    const float* mws[3] = {mw0, mw1, mw2};
    const float* src = (mat < 2) ? aws[ws] + mat * 65536 : mws[ws] + (mat - 2) * 65536;
    __shared__ float t[32][33];
    const int r0 = blockIdx.x * 32, c0 = blockIdx.y * 32;
    const int x = threadIdx.x, y = threadIdx.y;
    for (int i = 0; i < 32; i += 8)
        t[y + i][x] = src[(r0 + y + i) * 256 + c0 + x];
    __syncthreads();
    for (int i = 0; i < 32; i += 8) {
        float v = t[x][y + i];
        __nv_bfloat16 h = __float2bfloat16(v);
        float hf = __bfloat162float(h);
        g_Wth[ws][mat][(c0 + y + i) * 256 + r0 + x] = h;
        g_Wtl[ws][mat][(c0 + y + i) * 256 + r0 + x] = __float2bfloat16(v - hf);
    }
}

// =============== X transpose + bf16 split, batched ==========================
__global__ void xt_split(const float* __restrict__ x0, const float* __restrict__ x1,
                         const float* __restrict__ x2, const float* __restrict__ x3)
{
    const int br = blockIdx.z;
    const float* Xs[4] = {x0, x1, x2, x3};
    const float* X = Xs[br];
    __shared__ float t[32][33];
    const int r0 = blockIdx.x * 32, c0 = blockIdx.y * 32;
    const int x = threadIdx.x, y = threadIdx.y;
    for (int i = 0; i < 32; i += 8)
        t[y + i][x] = X[(r0 + y + i) * 256 + c0 + x];
    __syncthreads();
    for (int i = 0; i < 32; i += 8) {
        float v = t[x][y + i];
        __nv_bfloat16 h = __float2bfloat16(v);
        float hf = __bfloat162float(h);
        g_Xth[br][(c0 + y + i) * 4096 + r0 + x] = h;
        g_Xtl[br][(c0 + y + i) * 4096 + r0 + x] = __float2bfloat16(v - hf);
    }
}

// ---------------- BatchNorm stats (deterministic, batched) ------------------
__global__ void colstats()
{
    const int br = blockIdx.y, t = threadIdx.x;
    const float* H = g_Hm[br];
    int r0 = blockIdx.x * 128;
    float s = 0.0f, q = 0.0f;
    for (int r = r0; r < r0 + 128; ++r) {
        float v = H[r * 256 + t];
        s += v;
        q += v * v;
    }
    g_colpart[br][blockIdx.x * 512 + t] = s;
    g_colpart[br][blockIdx.x * 512 + 256 + t] = q;
}

__global__ void finalize_stats(const float* __restrict__ g0, const float* __restrict__ g1,
                               const float* __restrict__ g2, const float* __restrict__ g3)
{
    const int br = blockIdx.x, t = threadIdx.x;
    const float* Gs[4] = {g0, g1, g2, g3};
    const float* gamma = Gs[br];
    const float* beta = gamma + 256;
    float s = 0.0f, q = 0.0f;
    for (int b = 0; b < 32; ++b) {
        s += g_colpart[br][b * 512 + t];
        q += g_colpart[br][b * 512 + 256 + t];
    }
    float mu = s * (1.0f / (float)NN);
    float var = q * (1.0f / (float)NN) - mu * mu;
    float rstd = rsqrtf(var + 1e-5f);
    float sc = gamma[t] * rstd;
    g_bnscale[br][t] = sc;
    g_bnshift[br][t] = beta[t] - mu * sc;
}

// ---------------- MSE --------------------------------------------------------
__global__ void mse_partial()
{
    int t = threadIdx.x, b = blockIdx.x;
    float s0 = 0.0f, s1 = 0.0f, s2 = 0.0f;
    for (int i = b * 256 + t; i < ND; i += 256 * 256) {
        float ga = g_G[3][i];
        float d0 = g_G[0][i] - ga;
        float d1 = g_G[1][i] - ga;
        float d2 = g_G[2][i] - ga;
        s0 += d0 * d0;
        s1 += d1 * d1;
        s2 += d2 * d2;
    }
    __shared__ float r[3][256];
    r[0][t] = s0; r[1][t] = s1; r[2][t] = s2;
    __syncthreads();
    for (int o = 128; o > 0; o >>= 1) {
        if (t < o) {
            r[0][t] += r[0][t + o];
            r[1][t] += r[1][t + o];
            r[2][t] += r[2][t + o];
        }
        __syncthreads();
    }
    if (t == 0) {
        g_msepart[b * 3 + 0] = r[0][0];
        g_msepart[b * 3 + 1] = r[1][0];
        g_msepart[b * 3 + 2] = r[2][0];
    }
}

__global__ void mse_final(float* __restrict__ out)
{
    int t = threadIdx.x;
    __shared__ float r[256];
    for (int v = 0; v < 3; ++v) {
        r[t] = g_msepart[t * 3 + v];
        __syncthreads();
        for (int o = 128; o > 0; o >>= 1) {
            if (t < o) r[t] += r[t + o];
            __syncthreads();
        }
        if (t == 0) out[v] = r[0] * (1.0f / (float)ND);
        __syncthreads();
    }
}

// ---------------- host driver ------------------------------------------------
extern "C" void kernel_launch(void* const* d_in, const int* in_sizes, int n_in,
                              void* d_out, int out_size)
{
    const float* QV = (const float*)d_in[0];
    const float* Q  = (const float*)d_in[1];
    const float* V  = (const float*)d_in[2];
    const float* A  = (const float*)d_in[3];
    const float* adjW_qv  = (const float*)d_in[4];
    const float* adjb_qv  = (const float*)d_in[5];
    const float* mlpW_qv  = (const float*)d_in[6];
    const float* mlpb_qv  = (const float*)d_in[7];
    const float* mlpbn_qv = (const float*)d_in[8];
    const float* adjW_t   = (const float*)d_in[9];
    const float* adjb_t   = (const float*)d_in[10];
    const float* mlpW_t   = (const float*)d_in[11];
    const float* mlpb_t   = (const float*)d_in[12];
    const float* mlpbn_t  = (const float*)d_in[13];
    const float* adjW_v   = (const float*)d_in[14];
    const float* adjb_v   = (const float*)d_in[15];
    const float* mlpW_v   = (const float*)d_in[16];
    const float* mlpb_v   = (const float*)d_in[17];
    const float* mlpbn_v  = (const float*)d_in[18];

    cudaFuncSetAttribute(adj_mma, cudaFuncAttributeMaxDynamicSharedMemorySize, ADJ_SMEM);
    cudaFuncSetAttribute(thresh_mma, cudaFuncAttributeMaxDynamicSharedMemorySize, THR_SMEM);
    cudaFuncSetAttribute(gemm_mma<0, 0>, cudaFuncAttributeMaxDynamicSharedMemorySize, SM_SMEM);
    cudaFuncSetAttribute(gemm_mma<0, 1>, cudaFuncAttributeMaxDynamicSharedMemorySize, SM_SMEM);
    cudaFuncSetAttribute(gemm_mma<0, 2>, cudaFuncAttributeMaxDynamicSharedMemorySize, SM_SMEM);
    cudaFuncSetAttribute(gemm_mma<1, 3>, cudaFuncAttributeMaxDynamicSharedMemorySize, SM_SMEM);
    cudaFuncSetAttribute(gemm_mma<1, 4>, cudaFuncAttributeMaxDynamicSharedMemorySize, SM_SMEM);
    cudaFuncSetAttribute(gemm_mma<1, 5>, cudaFuncAttributeMaxDynamicSharedMemorySize, SM_SMEM);

    float *pX, *pH1, *pY, *pHm;
    cudaGetSymbolAddress((void**)&pX, g_X);
    cudaGetSymbolAddress((void**)&pH1, g_H1);
    cudaGetSymbolAddress((void**)&pY, g_Y);
    cudaGetSymbolAddress((void**)&pHm, g_Hm);

    const float* ab[4] = {adjb_qv, adjb_t, adjb_v, adjb_t};
    const float* mb[4] = {mlpb_qv, mlpb_t, mlpb_v, mlpb_t};
    const float* bn[4] = {mlpbn_qv, mlpbn_t, mlpbn_v, mlpbn_t};

    wt_split<<<dim3(8, 8, 24), dim3(32, 8)>>>(adjW_qv, adjW_t, adjW_v,
                                              mlpW_qv, mlpW_t, mlpW_v);

    const dim3 g_sm(2, 64, 4);
    for (int l = 0; l < LL; ++l) {
        const float* X0 = (l == 0) ? QV : pX;
        const float* X1 = (l == 0) ? Q : pX + (size_t)ND;
        const float* X2 = (l == 0) ? V : pX + 2 * (size_t)ND;
        const float* X3 = (l == 0) ? A : pX + 3 * (size_t)ND;

        gemm_mma<0, 0><<<g_sm, 256, SM_SMEM>>>(X0, X1, X2, X3, 0,
                                               ab[0], ab[1], ab[2], ab[3]);
        gemm_mma<0, 2><<<g_sm, 256, SM_SMEM>>>(
            pH1, pH1 + (size_t)ND, pH1 + 2 * (size_t)ND, pH1 + 3 * (size_t)ND, 1,
            ab[0] + 256, ab[1] + 256, ab[2] + 256, ab[3] + 256);
        colsum_part<<<dim3(32, 4), 256>>>();
        colsum_mean<<<4, 256>>>();
        adj_mma<<<dim3(NTB, 4), 256, ADJ_SMEM>>>();
        xt_split<<<dim3(128, 8, 4), dim3(32, 8)>>>(X0, X1, X2, X3);
        thresh_mma<<<dim3(32, KZ, 4), 256, THR_SMEM>>>();
        combine_Y<<<dim3(256, 4), 256>>>(X0, X1, X2, X3);

        gemm_mma<0, 1><<<g_sm, 256, SM_SMEM>>>(
            pY, pY + (size_t)ND, pY + 2 * (size_t)ND, pY + 3 * (size_t)ND, 2 + 2 * l,
            mb[0] + l * 512, mb[1] + l * 512, mb[2] + l * 512, mb[3] + l * 512);
        colstats<<<dim3(32, 4), 256>>>();
        finalize_stats<<<4, 256>>>(bn[0] + l * 512, bn[1] + l * 512,
                                   bn[2] + l * 512, bn[3] + l * 512);
        const float* c0 = mb[0] + l * 512 + 256;
        const float* c1 = mb[1] + l * 512 + 256;
        const float* c2 = mb[2] + l * 512 + 256;
        const float* c3 = mb[3] + l * 512 + 256;
        if (l == 0)
            gemm_mma<1, 3><<<g_sm, 256, SM_SMEM>>>(
                pHm, pHm + (size_t)ND, pHm + 2 * (size_t)ND, pHm + 3 * (size_t)ND,
                3 + 2 * l, c0, c1, c2, c3);
        else if (l == 1)
            gemm_mma<1, 4><<<g_sm, 256, SM_SMEM>>>(
                pHm, pHm + (size_t)ND, pHm + 2 * (size_t)ND, pHm + 3 * (size_t)ND,
                3 + 2 * l, c0, c1, c2, c3);
        else
            gemm_mma<1, 5><<<g_sm, 256, SM_SMEM>>>(
                pHm, pHm + (size_t)ND, pHm + 2 * (size_t)ND, pHm + 3 * (size_t)ND,
                3 + 2 * l, c0, c1, c2, c3);
    }

    mse_partial<<<256, 256>>>();
    mse_final<<<1, 256>>>((float*)d_out);
}